// round 12
// baseline (speedup 1.0000x reference)
#include <cuda_runtime.h>
#include <cuda_bf16.h>
#include <cuda_fp16.h>
#include <math.h>
#include <stdint.h>

// ---------------- problem constants ----------------
#define BB     4
#define TT     2048
#define DD     2048
#define HH     8
#define DK     128
#define DV     256
#define CHUNK  128
#define NCH    16
#define MROWS  (BB*TT)      // 8192
#define DHALF  (DD/2)       // 1024
#define SCALING 0.0625f
#define INV_NORM_GK (1.0f/16.0f)
#define NCHUNKS (BB*NCH*HH) // 512
#define NBLOBS  (BB*HH*4*NCH) // 2048
#define WTROWS 8192

// ---------------- scratch ----------------
__device__ float g_QK [(size_t)MROWS * 2048];
__device__ float g_GK [(size_t)MROWS * DHALF];
__device__ float g_KG1[(size_t)MROWS * 16];
__device__ float g_DEC[(size_t)BB * NCH * DHALF];
__device__ float g_G  [(size_t)MROWS * DD];
__device__ float g_O  [(size_t)MROWS * DD];
__device__ float g_U  [(size_t)NBLOBS * 8192];
__device__ __half g_XH [(size_t)MROWS * DD];
__device__ __half g_WTH[(size_t)WTROWS * DD];
__device__ __half g_WTL[(size_t)WTROWS * DD];
__device__ __half g_PH [(size_t)MROWS * DD];
__device__ __nv_bfloat16 g_QH [(size_t)MROWS * DHALF];
__device__ __nv_bfloat16 g_QL [(size_t)MROWS * DHALF];
__device__ __nv_bfloat16 g_KH [(size_t)MROWS * DHALF];
__device__ __nv_bfloat16 g_KL [(size_t)MROWS * DHALF];
__device__ __nv_bfloat16 g_KDH[(size_t)MROWS * DHALF];
__device__ __nv_bfloat16 g_KDL[(size_t)MROWS * DHALF];
__device__ __nv_bfloat16 g_VH [(size_t)MROWS * DD];
__device__ __nv_bfloat16 g_VL [(size_t)MROWS * DD];
__device__ __nv_bfloat16 g_AH [(size_t)NCHUNKS * CHUNK * CHUNK];
__device__ __nv_bfloat16 g_AL [(size_t)NCHUNKS * CHUNK * CHUNK];
__device__ __nv_bfloat16 g_SBH[(size_t)NBLOBS * 64 * 128];
__device__ __nv_bfloat16 g_SBL[(size_t)NBLOBS * 64 * 128];

// ================= helpers =================
__device__ __forceinline__ uint32_t smem_u32(const void* p) {
    uint32_t a;
    asm("{ .reg .u64 t; cvta.to.shared.u64 t, %1; cvt.u32.u64 %0, t; }" : "=r"(a) : "l"(p));
    return a;
}
__device__ __forceinline__ void cpasync16(uint32_t dst, const void* src) {
    asm volatile("cp.async.cg.shared.global [%0], [%1], 16;" :: "r"(dst), "l"(src) : "memory");
}
__device__ __forceinline__ void ldsm_x4(uint32_t* r, uint32_t addr) {
    asm volatile("ldmatrix.sync.aligned.m8n8.x4.shared.b16 {%0,%1,%2,%3}, [%4];"
                 : "=r"(r[0]), "=r"(r[1]), "=r"(r[2]), "=r"(r[3]) : "r"(addr));
}
__device__ __forceinline__ void mma16816(float* c, const uint32_t* a, const uint32_t* b) {
    asm volatile(
        "mma.sync.aligned.m16n8k16.row.col.f32.bf16.bf16.f32 "
        "{%0,%1,%2,%3}, {%4,%5,%6,%7}, {%8,%9}, {%0,%1,%2,%3};"
        : "+f"(c[0]), "+f"(c[1]), "+f"(c[2]), "+f"(c[3])
        : "r"(a[0]), "r"(a[1]), "r"(a[2]), "r"(a[3]), "r"(b[0]), "r"(b[1]));
}
__device__ __forceinline__ void mma16816h(float* c, const uint32_t* a, const uint32_t* b) {
    asm volatile(
        "mma.sync.aligned.m16n8k16.row.col.f32.f16.f16.f32 "
        "{%0,%1,%2,%3}, {%4,%5,%6,%7}, {%8,%9}, {%0,%1,%2,%3};"
        : "+f"(c[0]), "+f"(c[1]), "+f"(c[2]), "+f"(c[3])
        : "r"(a[0]), "r"(a[1]), "r"(a[2]), "r"(a[3]), "r"(b[0]), "r"(b[1]));
}
static __device__ __forceinline__ uint32_t sw128(uint32_t o) { return o ^ ((o >> 3) & 0x70); }

// acc[MF][4][4] += A_tile @ B_tile^T over K=128 (2 sw128 K-subtiles) [bf16]
template<int MF>
__device__ __forceinline__ void mma_combo(float (*acc)[4][4], uint32_t Ab, uint32_t abs_,
                                          uint32_t Bb, uint32_t bbs, int mw, int nw, int lane)
{
#pragma unroll
    for (int kb = 0; kb < 2; kb++) {
#pragma unroll
        for (int ks = 0; ks < 4; ks++) {
            uint32_t af[MF][4];
#pragma unroll
            for (int mf = 0; mf < MF; mf++) {
                int row = mw + mf * 16 + (lane & 15);
                uint32_t bo = (uint32_t)(row << 7) + (uint32_t)(ks << 5) + ((lane >> 4) << 4);
                ldsm_x4(af[mf], Ab + kb * abs_ + sw128(bo));
            }
            uint32_t bfr[4][2];
#pragma unroll
            for (int half = 0; half < 2; half++) {
                int i2 = lane >> 3;
                int row = nw + half * 16 + ((i2 >> 1) << 3) + (lane & 7);
                uint32_t bo = (uint32_t)(row << 7) + (uint32_t)(ks << 5) + ((i2 & 1) << 4);
                uint32_t r[4];
                ldsm_x4(r, Bb + kb * bbs + sw128(bo));
                bfr[half * 2][0] = r[0];     bfr[half * 2][1] = r[1];
                bfr[half * 2 + 1][0] = r[2]; bfr[half * 2 + 1][1] = r[3];
            }
#pragma unroll
            for (int mf = 0; mf < MF; mf++)
#pragma unroll
                for (int nf = 0; nf < 4; nf++)
                    mma16816(acc[mf][nf], af[mf], bfr[nf]);
        }
    }
}

// ======================================================================
// gemm2w: fp16 2-pass GEMM, 128x256 block tile, 2-stage pipeline.
// 8 warps as 2(m) x 4(n), 64x64 warp tiles (MF=4, NF=8).
// Epilogue regions by global col:
//   [0, ns1): fp32 -> C0 (stride ns1)
//   [ns1, ns2): bf16 split -> SHo/SLo (stride ns2-ns1)
//   [ns2, N): fp32 + bias -> C2 (stride N-ns2)
// ======================================================================
__global__ __launch_bounds__(256, 1)
void gemm2w(const __half* __restrict__ AHp,
            const __half* __restrict__ BHp, const __half* __restrict__ BLp,
            float* __restrict__ C0, __nv_bfloat16* __restrict__ SHo, __nv_bfloat16* __restrict__ SLo,
            float* __restrict__ C2, const float* __restrict__ bias,
            int M, int N, int K, int ns1, int ns2)
{
    extern __shared__ char smem[];
    const uint32_t sbase = smem_u32(smem);
    const int tid = threadIdx.x;
    const int wid = tid >> 5, lane = tid & 31;
    const int m0 = blockIdx.y * 128, n0 = blockIdx.x * 256;
    const int mw = (wid & 1) * 64, nw = (wid >> 1) * 64;
    const int TOT = K >> 6;

    float acc[4][8][4];
#pragma unroll
    for (int i = 0; i < 4; i++)
#pragma unroll
        for (int j = 0; j < 8; j++)
#pragma unroll
            for (int l = 0; l < 4; l++) acc[i][j][l] = 0.f;

    auto issue = [&](int it) {
        const int k0 = it << 6;
        const uint32_t st = sbase + (uint32_t)(it & 1) * 81920u;
#pragma unroll
        for (int l = 0; l < 4; l++) {
            int c = tid + (l << 8);
            int row = c >> 3;
            uint32_t dst = sw128((uint32_t)(row << 7) + ((c & 7) << 4));
            cpasync16(st + dst, AHp + (size_t)(m0 + row) * K + k0 + ((c & 7) << 3));
        }
#pragma unroll
        for (int l = 0; l < 8; l++) {
            int c = tid + (l << 8);
            int row = c >> 3;
            uint32_t dst = sw128((uint32_t)(row << 7) + ((c & 7) << 4));
            size_t bo = (size_t)(n0 + row) * K + k0 + ((c & 7) << 3);
            cpasync16(st + 16384 + dst, BHp + bo);
            cpasync16(st + 49152 + dst, BLp + bo);
        }
        asm volatile("cp.async.commit_group;" ::: "memory");
    };

    issue(0);
    for (int it = 0; it < TOT; it++) {
        if (it + 1 < TOT) {
            issue(it + 1);
            asm volatile("cp.async.wait_group 1;" ::: "memory");
        } else {
            asm volatile("cp.async.wait_group 0;" ::: "memory");
        }
        __syncthreads();
        const uint32_t st = sbase + (uint32_t)(it & 1) * 81920u;
#pragma unroll
        for (int ks = 0; ks < 4; ks++) {
            uint32_t afH[4][4], bfH[8][2], bfL[8][2];
#pragma unroll
            for (int mf = 0; mf < 4; mf++) {
                int row = mw + mf * 16 + (lane & 15);
                uint32_t bo = (uint32_t)(row << 7) + (uint32_t)(ks << 5) + ((lane >> 4) << 4);
                ldsm_x4(afH[mf], st + sw128(bo));
            }
#pragma unroll
            for (int hg = 0; hg < 4; hg++) {
                int i2 = lane >> 3;
                int row = nw + hg * 16 + ((i2 >> 1) << 3) + (lane & 7);
                uint32_t bo = (uint32_t)(row << 7) + (uint32_t)(ks << 5) + ((i2 & 1) << 4);
                uint32_t so = sw128(bo);
                uint32_t r[4];
                ldsm_x4(r, st + 16384 + so);
                bfH[hg * 2][0] = r[0];     bfH[hg * 2][1] = r[1];
                bfH[hg * 2 + 1][0] = r[2]; bfH[hg * 2 + 1][1] = r[3];
                ldsm_x4(r, st + 49152 + so);
                bfL[hg * 2][0] = r[0];     bfL[hg * 2][1] = r[1];
                bfL[hg * 2 + 1][0] = r[2]; bfL[hg * 2 + 1][1] = r[3];
            }
#pragma unroll
            for (int mf = 0; mf < 4; mf++)
#pragma unroll
                for (int nf = 0; nf < 8; nf++) {
                    mma16816h(acc[mf][nf], afH[mf], bfH[nf]);
                    mma16816h(acc[mf][nf], afH[mf], bfL[nf]);
                }
        }
        __syncthreads();
    }

    const int rb = m0 + mw + (lane >> 2);
    const int cb = n0 + nw + ((lane & 3) << 1);
    const int w0 = ns1, w1 = ns2 - ns1, w2 = N - ns2;
#pragma unroll
    for (int mf = 0; mf < 4; mf++) {
#pragma unroll
        for (int half = 0; half < 2; half++) {
            int row = rb + mf * 16 + half * 8;
#pragma unroll
            for (int nf = 0; nf < 8; nf++) {
                int col = cb + nf * 8;
                float vx = acc[mf][nf][half * 2 + 0];
                float vy = acc[mf][nf][half * 2 + 1];
                if (col < ns1) {
                    float2 v; v.x = vx; v.y = vy;
                    *(float2*)(C0 + (size_t)row * w0 + col) = v;
                } else if (col < ns2) {
                    int cc = col - ns1;
                    __nv_bfloat16 h0 = __float2bfloat16(vx);
                    __nv_bfloat16 h1 = __float2bfloat16(vy);
                    __nv_bfloat16 l0 = __float2bfloat16(vx - __bfloat162float(h0));
                    __nv_bfloat16 l1 = __float2bfloat16(vy - __bfloat162float(h1));
                    *(__nv_bfloat162*)(SHo + (size_t)row * w1 + cc) = __nv_bfloat162(h0, h1);
                    *(__nv_bfloat162*)(SLo + (size_t)row * w1 + cc) = __nv_bfloat162(l0, l1);
                } else {
                    int cc = col - ns2;
                    vx += bias[cc]; vy += bias[cc + 1];
                    float2 v; v.x = vx; v.y = vy;
                    *(float2*)(C2 + (size_t)row * w2 + cc) = v;
                }
            }
        }
    }
}

// ======================================================================
// akernel (verified): A = qd @ kexp^T, tril, split to bf16.
// ======================================================================
__global__ __launch_bounds__(256, 1)
void akernel(const __nv_bfloat16* __restrict__ QH, const __nv_bfloat16* __restrict__ QL,
             const __nv_bfloat16* __restrict__ KH, const __nv_bfloat16* __restrict__ KL,
             __nv_bfloat16* __restrict__ AH, __nv_bfloat16* __restrict__ AL)
{
    extern __shared__ char smemc[];
    const uint32_t sb = smem_u32(smemc);
    const uint32_t oQH = 0, oQL = 32768, oKH = 65536, oKL = 98304;
    const int tid = threadIdx.x;
    const int wid = tid >> 5, lane = tid & 31;
    const int h = blockIdx.x, ch = blockIdx.y, bb = blockIdx.z;
    const int m0 = bb * TT + ch * CHUNK;
    const int colQ = h * 128;
    const size_t chA = (size_t)((bb * NCH + ch) * HH + h) * 16384;

#pragma unroll
    for (int l = 0; l < 8; l++) {
        int idx = tid + (l << 8);
        int row = idx >> 4, u = idx & 15;
        int kb = u >> 3, sub = u & 7;
        uint32_t dst = (uint32_t)kb * 16384u + sw128((uint32_t)(row << 7) + (sub << 4));
        size_t so = (size_t)(m0 + row) * DHALF + colQ + kb * 64 + sub * 8;
        cpasync16(sb + oQH + dst, QH + so);
        cpasync16(sb + oQL + dst, QL + so);
        cpasync16(sb + oKH + dst, KH + so);
        cpasync16(sb + oKL + dst, KL + so);
    }
    asm volatile("cp.async.commit_group;" ::: "memory");
    asm volatile("cp.async.wait_group 0;" ::: "memory");
    __syncthreads();

    const int mw = (wid & 1) * 64, nw = (wid >> 1) * 32;
    float acc[4][4][4];
#pragma unroll
    for (int i = 0; i < 4; i++)
#pragma unroll
        for (int j = 0; j < 4; j++)
#pragma unroll
            for (int l = 0; l < 4; l++) acc[i][j][l] = 0.f;

    mma_combo<4>(acc, sb + oQH, 16384, sb + oKH, 16384, mw, nw, lane);
    mma_combo<4>(acc, sb + oQH, 16384, sb + oKL, 16384, mw, nw, lane);
    mma_combo<4>(acc, sb + oQL, 16384, sb + oKH, 16384, mw, nw, lane);

#pragma unroll
    for (int mf = 0; mf < 4; mf++) {
#pragma unroll
        for (int half = 0; half < 2; half++) {
            int i = mw + mf * 16 + half * 8 + (lane >> 2);
#pragma unroll
            for (int nf = 0; nf < 4; nf++) {
                int j = nw + nf * 8 + ((lane & 3) << 1);
                float v0 = (j     <= i) ? acc[mf][nf][half * 2 + 0] : 0.f;
                float v1 = (j + 1 <= i) ? acc[mf][nf][half * 2 + 1] : 0.f;
                __nv_bfloat16 h0 = __float2bfloat16(v0);
                __nv_bfloat16 h1 = __float2bfloat16(v1);
                __nv_bfloat16 l0 = __float2bfloat16(v0 - __bfloat162float(h0));
                __nv_bfloat16 l1 = __float2bfloat16(v1 - __bfloat162float(h1));
                size_t oi = chA + (size_t)i * 128 + j;
                *(__nv_bfloat162*)(AH + oi) = __nv_bfloat162(h0, h1);
                *(__nv_bfloat162*)(AL + oi) = __nv_bfloat162(l0, l1);
            }
        }
    }
}

// ======================================================================
// phase1 (verified R11): o_part = tril(A)@v -> O ; U = kd^T@v -> U blob.
// ======================================================================
__global__ __launch_bounds__(256, 1)
void phase1_kernel(const __nv_bfloat16* __restrict__ AH, const __nv_bfloat16* __restrict__ AL,
                   const __nv_bfloat16* __restrict__ KDH, const __nv_bfloat16* __restrict__ KDL,
                   const __nv_bfloat16* __restrict__ VH, const __nv_bfloat16* __restrict__ VL,
                   float* __restrict__ O, float* __restrict__ U)
{
    extern __shared__ char smemc[];
    const uint32_t sb = smem_u32(smemc);
    const uint32_t oAH = 0, oAL = 32768, oKT = 65536, oKTl = 98304;
    const uint32_t oVH = 131072, oVL = 147456;

    const int tid = threadIdx.x;
    const int wid = tid >> 5, lane = tid & 31;
    const int ch = blockIdx.x >> 2, vsl = blockIdx.x & 3;
    const int h = blockIdx.y, bb = blockIdx.z;
    const int m0 = bb * TT + ch * CHUNK;
    const int colQ = h * 128;
    const int colV = h * 256 + vsl * 64;
    const size_t chA = (size_t)((bb * NCH + ch) * HH + h) * 16384;
    const size_t ublob = (size_t)(((bb * HH + h) * 4 + vsl) * NCH + ch) * 8192;
    const int mw = (wid & 3) * 32, nw = (wid >> 2) * 32;

#pragma unroll
    for (int l = 0; l < 8; l++) {
        int idx = tid + (l << 8);
        int row = idx >> 4, u = idx & 15;
        int kb = u >> 3, sub = u & 7;
        uint32_t dst = (uint32_t)kb * 16384u + sw128((uint32_t)(row << 7) + (sub << 4));
        size_t sa = chA + (size_t)row * 128 + kb * 64 + sub * 8;
        cpasync16(sb + oAH + dst, AH + sa);
        cpasync16(sb + oAL + dst, AL + sa);
    }
    asm volatile("cp.async.commit_group;" ::: "memory");

#pragma unroll
    for (int l = 0; l < 32; l++) {
        int idx = tid + (l << 8);
        int j = idx >> 6, d = (idx & 63) << 1;
        uint32_t wv = *(const uint32_t*)(KDH + (size_t)(m0 + j) * DHALF + colQ + d);
        uint32_t wl = *(const uint32_t*)(KDL + (size_t)(m0 + j) * DHALF + colQ + d);
        uint32_t kbo = (uint32_t)(j >> 6) * 16384u;
        uint32_t off0 = kbo + sw128((uint32_t)(d << 7) + ((j & 63) << 1));
        uint32_t off1 = kbo + sw128((uint32_t)((d + 1) << 7) + ((j & 63) << 1));
        *(unsigned short*)(smemc + oKT  + off0) = (unsigned short)(wv & 0xffff);
        *(unsigned short*)(smemc + oKT  + off1) = (unsigned short)(wv >> 16);
        *(unsigned short*)(smemc + oKTl + off0) = (unsigned short)(wl & 0xffff);
        *(unsigned short*)(smemc + oKTl + off1) = (unsigned short)(wl >> 16);
    }
#pragma unroll
    for (int l = 0; l < 16; l++) {
        int idx = tid + (l << 8);
        int j = idx >> 5, n = (idx & 31) << 1;
        uint32_t wv = *(const uint32_t*)(VH + (size_t)(m0 + j) * DD + colV + n);
        uint32_t wl = *(const uint32_t*)(VL + (size_t)(m0 + j) * DD + colV + n);
        uint32_t kbo = (uint32_t)(j >> 6) * 8192u;
        uint32_t off0 = kbo + sw128((uint32_t)(n << 7) + ((j & 63) << 1));
        uint32_t off1 = kbo + sw128((uint32_t)((n + 1) << 7) + ((j & 63) << 1));
        *(unsigned short*)(smemc + oVH + off0) = (unsigned short)(wv & 0xffff);
        *(unsigned short*)(smemc + oVH + off1) = (unsigned short)(wv >> 16);
        *(unsigned short*)(smemc + oVL + off0) = (unsigned short)(wl & 0xffff);
        *(unsigned short*)(smemc + oVL + off1) = (unsigned short)(wl >> 16);
    }
    asm volatile("cp.async.wait_group 0;" ::: "memory");
    __syncthreads();

    float acc[2][4][4];
#pragma unroll
    for (int i = 0; i < 2; i++)
#pragma unroll
        for (int j = 0; j < 4; j++)
#pragma unroll
            for (int l = 0; l < 4; l++) acc[i][j][l] = 0.f;
    mma_combo<2>(acc, sb + oAH, 16384, sb + oVH, 8192, mw, nw, lane);
    mma_combo<2>(acc, sb + oAH, 16384, sb + oVL, 8192, mw, nw, lane);
    mma_combo<2>(acc, sb + oAL, 16384, sb + oVH, 8192, mw, nw, lane);
#pragma unroll
    for (int mf = 0; mf < 2; mf++) {
#pragma unroll
        for (int half = 0; half < 2; half++) {
            int row = m0 + mw + mf * 16 + half * 8 + (lane >> 2);
#pragma unroll
            for (int nf = 0; nf < 4; nf++) {
                int col = colV + nw + nf * 8 + ((lane & 3) << 1);
                float2 v;
                v.x = acc[mf][nf][half * 2 + 0];
                v.y = acc[mf][nf][half * 2 + 1];
                *(float2*)&O[(size_t)row * DD + col] = v;
            }
        }
    }

    float uacc[2][4][4];
#pragma unroll
    for (int i = 0; i < 2; i++)
#pragma unroll
        for (int j = 0; j < 4; j++)
#pragma unroll
            for (int l = 0; l < 4; l++) uacc[i][j][l] = 0.f;
    mma_combo<2>(uacc, sb + oKT,  16384, sb + oVH, 8192, mw, nw, lane);
    mma_combo<2>(uacc, sb + oKT,  16384, sb + oVL, 8192, mw, nw, lane);
    mma_combo<2>(uacc, sb + oKTl, 16384, sb + oVH, 8192, mw, nw, lane);
#pragma unroll
    for (int mf = 0; mf < 2; mf++) {
#pragma unroll
        for (int half = 0; half < 2; half++) {
            int d = mw + mf * 16 + half * 8 + (lane >> 2);
            uint32_t kb = (uint32_t)(d >> 6) * 4096u;
            uint32_t d2b = (uint32_t)((d & 63) << 1);
#pragma unroll
            for (int nf = 0; nf < 4; nf++) {
                int n = nw + nf * 8 + ((lane & 3) << 1);
                uint32_t i0 = kb + (sw128(((uint32_t)n << 7) + d2b) >> 1);
                uint32_t i1 = kb + (sw128(((uint32_t)(n + 1) << 7) + d2b) >> 1);
                U[ublob + i0] = uacc[mf][nf][half * 2 + 0];
                U[ublob + i1] = uacc[mf][nf][half * 2 + 1];
            }
        }
    }
}

// ======================================================================
// scan (verified R11)
// ======================================================================
__global__ __launch_bounds__(256, 1)
void scan_kernel(const float* __restrict__ U, const float* __restrict__ DEC,
                 __nv_bfloat16* __restrict__ SBH, __nv_bfloat16* __restrict__ SBL)
{
    __shared__ float sdec[128];
    const int t = threadIdx.x;
    const int vsl = blockIdx.x, h = blockIdx.y, bb = blockIdx.z;
    const int blobbase = ((bb * HH + h) * 4 + vsl) * NCH;
    const int colQ = h * 128;

    int dbase[8];
#pragma unroll
    for (int g = 0; g < 8; g++) {
        uint32_t ibase = (uint32_t)(t + g * 256) * 4;
        uint32_t braw = sw128((ibase & 4095) * 2);
        dbase[g] = (int)(ibase >> 12) * 64 + (int)((braw & 127) >> 1);
    }

    float S[32];
#pragma unroll
    for (int i = 0; i < 32; i++) S[i] = 0.f;

    for (int ch = 0; ch < NCH; ch++) {
        if (t < 128) sdec[t] = DEC[(size_t)(bb * NCH + ch) * DHALF + colQ + t];
        const size_t blob = (size_t)(blobbase + ch) * 8192;
#pragma unroll
        for (int g = 0; g < 8; g++) {
            uint32_t ibase = (uint32_t)(t + g * 256) * 4;
            float v0 = S[g * 4 + 0], v1 = S[g * 4 + 1], v2 = S[g * 4 + 2], v3 = S[g * 4 + 3];
            __nv_bfloat16 h0 = __float2bfloat16(v0), h1 = __float2bfloat16(v1);
            __nv_bfloat16 h2 = __float2bfloat16(v2), h3 = __float2bfloat16(v3);
            *(__nv_bfloat162*)(SBH + blob + ibase)     = __nv_bfloat162(h0, h1);
            *(__nv_bfloat162*)(SBH + blob + ibase + 2) = __nv_bfloat162(h2, h3);
            __nv_bfloat16 l0 = __float2bfloat16(v0 - __bfloat162float(h0));
            __nv_bfloat16 l1 = __float2bfloat16(v1 - __bfloat162float(h1));
            __nv_bfloat16 l2 = __float2bfloat16(v2 - __bfloat162float(h2));
            __nv_bfloat16 l3 = __float2bfloat16(v3 - __bfloat162float(h3));
            *(__nv_bfloat162*)(SBL + blob + ibase)     = __nv_bfloat162(l0, l1);
            *(__nv_bfloat162*)(SBL + blob + ibase + 2) = __nv_bfloat162(l2, l3);
        }
        __syncthreads();
#pragma unroll
        for (int g = 0; g < 8; g++) {
            uint32_t ibase = (uint32_t)(t + g * 256) * 4;
            float4 u = *(const float4*)(U + blob + ibase);
            int d0 = dbase[g];
            S[g * 4 + 0] = sdec[d0 + 0] * S[g * 4 + 0] + u.x;
            S[g * 4 + 1] = sdec[d0 + 1] * S[g * 4 + 1] + u.y;
            S[g * 4 + 2] = sdec[d0 + 2] * S[g * 4 + 2] + u.z;
            S[g * 4 + 3] = sdec[d0 + 3] * S[g * 4 + 3] + u.w;
        }
        __syncthreads();
    }
}

// ======================================================================
// o2 (verified R11): O += qd @ S_ch
// ======================================================================
__global__ __launch_bounds__(256, 1)
void o2_kernel(const __nv_bfloat16* __restrict__ QH, const __nv_bfloat16* __restrict__ QL,
               const __nv_bfloat16* __restrict__ SBH, const __nv_bfloat16* __restrict__ SBL,
               float* __restrict__ O)
{
    extern __shared__ char smemc[];
    const uint32_t sb = smem_u32(smemc);
    const uint32_t oQH = 0, oQL = 32768, oSH = 65536, oSL = 81920;

    const int tid = threadIdx.x;
    const int wid = tid >> 5, lane = tid & 31;
    const int ch = blockIdx.x >> 2, vsl = blockIdx.x & 3;
    const int h = blockIdx.y, bb = blockIdx.z;
    const int m0 = bb * TT + ch * CHUNK;
    const int colQ = h * 128;
    const int colV = h * 256 + vsl * 64;
    const size_t blob = (size_t)(((bb * HH + h) * 4 + vsl) * NCH + ch) * 8192;
    const int mw = (wid & 3) * 32, nw = (wid >> 2) * 32;

#pragma unroll
    for (int l = 0; l < 8; l++) {
        int idx = tid + (l << 8);
        int row = idx >> 4, u = idx & 15;
        int kb = u >> 3, sub = u & 7;
        uint32_t dst = (uint32_t)kb * 16384u + sw128((uint32_t)(row << 7) + (sub << 4));
        size_t so = (size_t)(m0 + row) * DHALF + colQ + kb * 64 + sub * 8;
        cpasync16(sb + oQH + dst, QH + so);
        cpasync16(sb + oQL + dst, QL + so);
    }
#pragma unroll
    for (int l = 0; l < 4; l++) {
        int i = tid + (l << 8);
        cpasync16(sb + oSH + (i << 4), SBH + blob + (size_t)i * 8);
        cpasync16(sb + oSL + (i << 4), SBL + blob + (size_t)i * 8);
    }
    asm volatile("cp.async.commit_group;" ::: "memory");
    asm volatile("cp.async.wait_group 0;" ::: "memory");
    __syncthreads();

    float acc[2][4][4];
#pragma unroll
    for (int i = 0; i < 2; i++)
#pragma unroll
        for (int j = 0; j < 4; j++)
#pragma unroll
            for (int l = 0; l < 4; l++) acc[i][j][l] = 0.f;

    mma_combo<2>(acc, sb + oQH, 16384, sb + oSH, 8192, mw, nw, lane);
    mma_combo<2>(acc, sb + oQH, 16384, sb + oSL, 8192, mw, nw, lane);
    mma_combo<2>(acc, sb + oQL, 16384, sb + oSH, 8192, mw, nw, lane);

#pragma unroll
    for (int mf = 0; mf < 2; mf++) {
#pragma unroll
        for (int half = 0; half < 2; half++) {
            int row = m0 + mw + mf * 16 + half * 8 + (lane >> 2);
#pragma unroll
            for (int nf = 0; nf < 4; nf++) {
                int col = colV + nw + nf * 8 + ((lane & 3) << 1);
                float2 v = *(float2*)&O[(size_t)row * DD + col];
                v.x += acc[mf][nf][half * 2 + 0];
                v.y += acc[mf][nf][half * 2 + 1];
                *(float2*)&O[(size_t)row * DD + col] = v;
            }
        }
    }
}

// ======================================================================
// x -> fp16
// ======================================================================
__global__ void xhalf(const float4* __restrict__ X, __half* __restrict__ H, int n4)
{
    int i = blockIdx.x * blockDim.x + threadIdx.x;
    if (i >= n4) return;
    float4 v = X[i];
    __half2* Hp = (__half2*)H;
    Hp[i * 2]     = __floats2half2_rn(v.x, v.y);
    Hp[i * 2 + 1] = __floats2half2_rn(v.z, v.w);
}

// ======================================================================
// transpose W -> combined WT fp16 hi/lo
// ======================================================================
__global__ void wsplit_t(const float* __restrict__ W, __half* __restrict__ Th,
                         __half* __restrict__ Tl, int K, int N, int rowoff, float alpha)
{
    __shared__ float t[32][33];
    const int n0 = blockIdx.x * 32, k0 = blockIdx.y * 32;
    const int tx = threadIdx.x, ty = threadIdx.y;
#pragma unroll
    for (int i = 0; i < 4; i++) {
        int k = ty + i * 8;
        t[k][tx] = W[(size_t)(k0 + k) * N + n0 + tx];
    }
    __syncthreads();
#pragma unroll
    for (int i = 0; i < 4; i++) {
        int n = ty + i * 8;
        float v = t[tx][n] * alpha;
        __half h = __float2half(v);
        size_t oi = (size_t)(rowoff + n0 + n) * K + k0 + tx;
        Th[oi] = h;
        Tl[oi] = __float2half(v - __half2float(h));
    }
}

// ======================================================================
// kg1
// ======================================================================
__global__ void kg1_kernel(const float* __restrict__ x, const float* __restrict__ W1,
                           float* __restrict__ out)
{
    const int wid = threadIdx.x >> 5, lane = threadIdx.x & 31;
    const int row = blockIdx.x * 8 + wid;
    const float* xp = x + (size_t)row * DD;
    float acc[16];
#pragma unroll
    for (int c = 0; c < 16; c++) acc[c] = 0.f;
    for (int k = lane; k < DD; k += 32) {
        float xv = xp[k];
        const float4* wp = (const float4*)(W1 + (size_t)k * 16);
        float4 w0 = wp[0], w1 = wp[1], w2 = wp[2], w3 = wp[3];
        acc[0]  += xv * w0.x; acc[1]  += xv * w0.y; acc[2]  += xv * w0.z; acc[3]  += xv * w0.w;
        acc[4]  += xv * w1.x; acc[5]  += xv * w1.y; acc[6]  += xv * w1.z; acc[7]  += xv * w1.w;
        acc[8]  += xv * w2.x; acc[9]  += xv * w2.y; acc[10] += xv * w2.z; acc[11] += xv * w2.w;
        acc[12] += xv * w3.x; acc[13] += xv * w3.y; acc[14] += xv * w3.z; acc[15] += xv * w3.w;
    }
#pragma unroll
    for (int c = 0; c < 16; c++) {
        float v = acc[c];
#pragma unroll
        for (int off = 16; off; off >>= 1) v += __shfl_xor_sync(0xFFFFFFFFu, v, off);
        if (lane == 0) out[(size_t)row * 16 + c] = v;
    }
}

// ======================================================================
// gk
// ======================================================================
__global__ void gk_kernel(const float* __restrict__ KG1,
                          const float* __restrict__ W2,
                          const float* __restrict__ b2,
                          float* __restrict__ GK)
{
    __shared__ float a[16];
    int m = blockIdx.x;
    if (threadIdx.x < 16) a[threadIdx.x] = KG1[(size_t)m * 16 + threadIdx.x];
    __syncthreads();
    for (int c = threadIdx.x; c < DHALF; c += 128) {
        float z = b2[c];
#pragma unroll
        for (int r = 0; r < 16; r++) z = fmaf(a[r], W2[(size_t)r * DHALF + c], z);
        float e = __expf(-fabsf(z));
        float l = __logf(1.f + e);
        float ls = (z >= 0.f) ? -l : (z - l);
        GK[(size_t)m * DHALF + c] = ls * INV_NORM_GK;
    }
}

// ======================================================================
// prep
// ======================================================================
__global__ void prep_kernel(const float* __restrict__ QK,
                            const float* __restrict__ GK,
                            __nv_bfloat16* __restrict__ QHo, __nv_bfloat16* __restrict__ QLo,
                            __nv_bfloat16* __restrict__ KHo, __nv_bfloat16* __restrict__ KLo,
                            __nv_bfloat16* __restrict__ KDHo, __nv_bfloat16* __restrict__ KDLo,
                            float* __restrict__ DEC)
{
    int g = blockIdx.x * blockDim.x + threadIdx.x;
    int col = g & (DHALF - 1);
    int bc  = g >> 10;
    int row0 = ((bc >> 4) * TT) + ((bc & 15) * CHUNK);
    size_t baseg = (size_t)row0 * DHALF + col;
    size_t baseq = (size_t)row0 * 2048 + col;

    float gs = 0.f;
#pragma unroll 4
    for (int i = 0; i < CHUNK; i++) gs += GK[baseg + (size_t)i * DHALF];
    float egs = __expf(gs);

    float gc = 0.f;
    for (int i = 0; i < CHUNK; i++) {
        size_t idx = baseg + (size_t)i * DHALF;
        size_t qdx = baseq + (size_t)i * 2048;
        gc += GK[idx];
        float eg = __expf(gc);
        float qd = QK[qdx] * eg;
        float kv = QK[qdx + 1024];
        float ke = __fdividef(kv, eg);
        float kd = ke * egs;
        __nv_bfloat16 qh = __float2bfloat16(qd);
        __nv_bfloat16 kh = __float2bfloat16(ke);
        __nv_bfloat16 dh = __float2bfloat16(kd);
        QHo[idx]  = qh; QLo[idx]  = __float2bfloat16(qd - __bfloat162float(qh));
        KHo[idx]  = kh; KLo[idx]  = __float2bfloat16(ke - __bfloat162float(kh));
        KDHo[idx] = dh; KDLo[idx] = __float2bfloat16(kd - __bfloat162float(dh));
    }
    DEC[(size_t)bc * DHALF + col] = egs;
}

// ======================================================================
// norm * silu -> fp16
// ======================================================================
__global__ void norm_gate_kernel(const float* __restrict__ O,
                                 const float* __restrict__ G,
                                 __half* __restrict__ PH)
{
    int m = blockIdx.x, h = blockIdx.y;
    int tid = threadIdx.x;
    size_t idx = (size_t)m * DD + h * DV + tid;
    float v = O[idx];
    float s = v, s2 = v * v;
#pragma unroll
    for (int off = 16; off; off >>= 1) {
        s  += __shfl_xor_sync(0xFFFFFFFFu, s,  off);
        s2 += __shfl_xor_sync(0xFFFFFFFFu, s2, off);
    }
    __shared__ float ws[8], ws2[8];
    int w = tid >> 5, l = tid & 31;
    if (l == 0) { ws[w] = s; ws2[w] = s2; }
    __syncthreads();
    float ts = 0.f, ts2 = 0.f;
#pragma unroll
    for (int i = 0; i < 8; i++) { ts += ws[i]; ts2 += ws2[i]; }
    float mu = ts * (1.f / 256.f);
    float var = ts2 * (1.f / 256.f) - mu * mu;
    float nv = (v - mu) * rsqrtf(var + 1e-5f);
    float gt = G[idx];
    float sg = gt / (1.f + __expf(-gt));
    PH[idx] = __float2half(sg * nv);
}

// ======================================================================
extern "C" void kernel_launch(void* const* d_in, const int* in_sizes, int n_in,
                              void* d_out, int out_size)
{
    const float* x    = (const float*)d_in[0];
    const float* Wq   = (const float*)d_in[1];
    const float* Wk   = (const float*)d_in[2];
    const float* Wkg1 = (const float*)d_in[3];
    const float* Wkg2 = (const float*)d_in[4];
    const float* bkg2 = (const float*)d_in[5];
    const float* Wv   = (const float*)d_in[6];
    const float* Wg   = (const float*)d_in[7];
    const float* bg   = (const float*)d_in[8];
    const float* Wo   = (const float*)d_in[9];
    float* out = (float*)d_out;

    float *pQK, *pGK, *pKG1, *pDEC, *pG, *pO, *pU;
    __half *pXH, *pWTH, *pWTL, *pPH;
    __nv_bfloat16 *pQH, *pQL, *pKH, *pKL, *pKDH, *pKDL, *pVH, *pVL, *pAH, *pAL, *pSBH, *pSBL;
    cudaGetSymbolAddress((void**)&pQK,  g_QK);
    cudaGetSymbolAddress((void**)&pGK,  g_GK);
    cudaGetSymbolAddress((void**)&pKG1, g_KG1);
    cudaGetSymbolAddress((void**)&pDEC, g_DEC);
    cudaGetSymbolAddress((void**)&pG,   g_G);
    cudaGetSymbolAddress((void**)&pO,   g_O);
    cudaGetSymbolAddress((void**)&pU,   g_U);
    cudaGetSymbolAddress((void**)&pXH,  g_XH);
    cudaGetSymbolAddress((void**)&pWTH, g_WTH);
    cudaGetSymbolAddress((void**)&pWTL, g_WTL);
    cudaGetSymbolAddress((void**)&pPH,  g_PH);
    cudaGetSymbolAddress((void**)&pQH,  g_QH);
    cudaGetSymbolAddress((void**)&pQL,  g_QL);
    cudaGetSymbolAddress((void**)&pKH,  g_KH);
    cudaGetSymbolAddress((void**)&pKL,  g_KL);
    cudaGetSymbolAddress((void**)&pKDH, g_KDH);
    cudaGetSymbolAddress((void**)&pKDL, g_KDL);
    cudaGetSymbolAddress((void**)&pVH,  g_VH);
    cudaGetSymbolAddress((void**)&pVL,  g_VL);
    cudaGetSymbolAddress((void**)&pAH,  g_AH);
    cudaGetSymbolAddress((void**)&pAL,  g_AL);
    cudaGetSymbolAddress((void**)&pSBH, g_SBH);
    cudaGetSymbolAddress((void**)&pSBL, g_SBL);

    cudaFuncSetAttribute(gemm2w,        cudaFuncAttributeMaxDynamicSharedMemorySize, 163840);
    cudaFuncSetAttribute(akernel,       cudaFuncAttributeMaxDynamicSharedMemorySize, 131072);
    cudaFuncSetAttribute(phase1_kernel, cudaFuncAttributeMaxDynamicSharedMemorySize, 163840);
    cudaFuncSetAttribute(o2_kernel,     cudaFuncAttributeMaxDynamicSharedMemorySize, 98304);

    dim3 tb(32, 8);
    int n4 = MROWS * DD / 4;

    // x -> fp16 ; weights -> combined WT fp16 hi/lo (Q|K*scale|V|G|O)
    xhalf<<<(n4 + 255) / 256, 256>>>((const float4*)x, pXH, n4);
    kg1_kernel<<<MROWS / 8, 256>>>(x, Wkg1, pKG1);
    wsplit_t<<<dim3(DHALF / 32, DD / 32), tb>>>(Wq, pWTH, pWTL, DD, DHALF, 0, 1.0f);
    wsplit_t<<<dim3(DHALF / 32, DD / 32), tb>>>(Wk, pWTH, pWTL, DD, DHALF, 1024, SCALING);
    wsplit_t<<<dim3(DD / 32, DD / 32), tb>>>(Wv, pWTH, pWTL, DD, DD, 2048, 1.0f);
    wsplit_t<<<dim3(DD / 32, DD / 32), tb>>>(Wg, pWTH, pWTL, DD, DD, 4096, 1.0f);
    wsplit_t<<<dim3(DD / 32, DD / 32), tb>>>(Wo, pWTH, pWTL, DD, DD, 6144, 1.0f);

    // fused Q+K+V+G projection (N=6144): QK fp32 | V bf16-split | G fp32+bias
    gemm2w<<<dim3(6144 / 256, MROWS / 128), 256, 163840>>>(pXH, pWTH, pWTL,
        pQK, pVH, pVL, pG, bg, MROWS, 6144, DD, 2048, 4096);

    // gk + decay precompute
    gk_kernel<<<MROWS, 128>>>(pKG1, Wkg2, bkg2, pGK);
    prep_kernel<<<256, 256>>>(pQK, pGK, pQH, pQL, pKH, pKL, pKDH, pKDL, pDEC);

    // A chunks
    akernel<<<dim3(HH, NCH, BB), 256, 131072>>>(pQH, pQL, pKH, pKL, pAH, pAL);

    // parallel: O_intra + U chunks
    phase1_kernel<<<dim3(NCH * 4, HH, BB), 256, 163840>>>(pAH, pAL, pKDH, pKDL,
                                                          pVH, pVL, pO, pU);
    // fast elementwise scan -> S blobs
    scan_kernel<<<dim3(4, HH, BB), 256>>>(pU, pDEC, pSBH, pSBL);
    // parallel: O += qd @ S
    o2_kernel<<<dim3(NCH * 4, HH, BB), 256, 98304>>>(pQH, pQL, pSBH, pSBL, pO);

    // groupnorm + silu gate -> fp16
    norm_gate_kernel<<<dim3(MROWS, HH), 256>>>(pO, pG, pPH);

    // output projection (fp32 out): region0 only (ns1 = N)
    gemm2w<<<dim3(2048 / 256, MROWS / 128), 256, 163840>>>(pPH,
        pWTH + (size_t)6144 * DD, pWTL + (size_t)6144 * DD,
        out, nullptr, nullptr, nullptr, nullptr, MROWS, 2048, DD, 2048, 2048);
}

// round 13
// speedup vs baseline: 1.0531x; 1.0531x over previous
#include <cuda_runtime.h>
#include <cuda_bf16.h>
#include <cuda_fp16.h>
#include <math.h>
#include <stdint.h>

// ---------------- problem constants ----------------
#define BB     4
#define TT     2048
#define DD     2048
#define HH     8
#define DK     128
#define DV     256
#define CHUNK  128
#define NCH    16
#define MROWS  (BB*TT)      // 8192
#define DHALF  (DD/2)       // 1024
#define SCALING 0.0625f
#define INV_NORM_GK (1.0f/16.0f)
#define NCHUNKS (BB*NCH*HH) // 512
#define NBLOBS  (BB*HH*4*NCH) // 2048
#define WTROWS 8192

// ---------------- scratch ----------------
__device__ float g_QK [(size_t)MROWS * 2048];
__device__ float g_GK [(size_t)MROWS * DHALF];
__device__ float g_KG1[(size_t)MROWS * 16];
__device__ float g_DEC[(size_t)BB * NCH * DHALF];
__device__ float g_G  [(size_t)MROWS * DD];
__device__ float g_O  [(size_t)MROWS * DD];
__device__ float g_U  [(size_t)NBLOBS * 8192];
__device__ __half g_XH [(size_t)MROWS * DD];
__device__ __half g_WTH[(size_t)WTROWS * DD];
__device__ __half g_WTL[(size_t)WTROWS * DD];
__device__ __half g_PH [(size_t)MROWS * DD];
__device__ __nv_bfloat16 g_QH [(size_t)MROWS * DHALF];
__device__ __nv_bfloat16 g_QL [(size_t)MROWS * DHALF];
__device__ __nv_bfloat16 g_KH [(size_t)MROWS * DHALF];
__device__ __nv_bfloat16 g_KL [(size_t)MROWS * DHALF];
__device__ __nv_bfloat16 g_KDH[(size_t)MROWS * DHALF];
__device__ __nv_bfloat16 g_KDL[(size_t)MROWS * DHALF];
__device__ __nv_bfloat16 g_VH [(size_t)MROWS * DD];
__device__ __nv_bfloat16 g_VL [(size_t)MROWS * DD];
__device__ __nv_bfloat16 g_AH [(size_t)NCHUNKS * CHUNK * CHUNK];
__device__ __nv_bfloat16 g_AL [(size_t)NCHUNKS * CHUNK * CHUNK];
__device__ __nv_bfloat16 g_SBH[(size_t)NBLOBS * 64 * 128];
__device__ __nv_bfloat16 g_SBL[(size_t)NBLOBS * 64 * 128];

// ================= helpers =================
__device__ __forceinline__ uint32_t smem_u32(const void* p) {
    uint32_t a;
    asm("{ .reg .u64 t; cvta.to.shared.u64 t, %1; cvt.u32.u64 %0, t; }" : "=r"(a) : "l"(p));
    return a;
}
__device__ __forceinline__ void cpasync16(uint32_t dst, const void* src) {
    asm volatile("cp.async.cg.shared.global [%0], [%1], 16;" :: "r"(dst), "l"(src) : "memory");
}
__device__ __forceinline__ void ldsm_x4(uint32_t* r, uint32_t addr) {
    asm volatile("ldmatrix.sync.aligned.m8n8.x4.shared.b16 {%0,%1,%2,%3}, [%4];"
                 : "=r"(r[0]), "=r"(r[1]), "=r"(r[2]), "=r"(r[3]) : "r"(addr));
}
__device__ __forceinline__ void mma16816(float* c, const uint32_t* a, const uint32_t* b) {
    asm volatile(
        "mma.sync.aligned.m16n8k16.row.col.f32.bf16.bf16.f32 "
        "{%0,%1,%2,%3}, {%4,%5,%6,%7}, {%8,%9}, {%0,%1,%2,%3};"
        : "+f"(c[0]), "+f"(c[1]), "+f"(c[2]), "+f"(c[3])
        : "r"(a[0]), "r"(a[1]), "r"(a[2]), "r"(a[3]), "r"(b[0]), "r"(b[1]));
}
__device__ __forceinline__ void mma16816h(float* c, const uint32_t* a, const uint32_t* b) {
    asm volatile(
        "mma.sync.aligned.m16n8k16.row.col.f32.f16.f16.f32 "
        "{%0,%1,%2,%3}, {%4,%5,%6,%7}, {%8,%9}, {%0,%1,%2,%3};"
        : "+f"(c[0]), "+f"(c[1]), "+f"(c[2]), "+f"(c[3])
        : "r"(a[0]), "r"(a[1]), "r"(a[2]), "r"(a[3]), "r"(b[0]), "r"(b[1]));
}
static __device__ __forceinline__ uint32_t sw128(uint32_t o) { return o ^ ((o >> 3) & 0x70); }

// acc[MF][4][4] += A_tile @ B_tile^T over K=128 (2 sw128 K-subtiles) [bf16]
template<int MF>
__device__ __forceinline__ void mma_combo(float (*acc)[4][4], uint32_t Ab, uint32_t abs_,
                                          uint32_t Bb, uint32_t bbs, int mw, int nw, int lane)
{
#pragma unroll
    for (int kb = 0; kb < 2; kb++) {
#pragma unroll
        for (int ks = 0; ks < 4; ks++) {
            uint32_t af[MF][4];
#pragma unroll
            for (int mf = 0; mf < MF; mf++) {
                int row = mw + mf * 16 + (lane & 15);
                uint32_t bo = (uint32_t)(row << 7) + (uint32_t)(ks << 5) + ((lane >> 4) << 4);
                ldsm_x4(af[mf], Ab + kb * abs_ + sw128(bo));
            }
            uint32_t bfr[4][2];
#pragma unroll
            for (int half = 0; half < 2; half++) {
                int i2 = lane >> 3;
                int row = nw + half * 16 + ((i2 >> 1) << 3) + (lane & 7);
                uint32_t bo = (uint32_t)(row << 7) + (uint32_t)(ks << 5) + ((i2 & 1) << 4);
                uint32_t r[4];
                ldsm_x4(r, Bb + kb * bbs + sw128(bo));
                bfr[half * 2][0] = r[0];     bfr[half * 2][1] = r[1];
                bfr[half * 2 + 1][0] = r[2]; bfr[half * 2 + 1][1] = r[3];
            }
#pragma unroll
            for (int mf = 0; mf < MF; mf++)
#pragma unroll
                for (int nf = 0; nf < 4; nf++)
                    mma16816(acc[mf][nf], af[mf], bfr[nf]);
        }
    }
}

// ======================================================================
// gemm2h: fp16 2-pass GEMM (R11-proven shape: 128x128, 3-stage, 256 thr).
// 3-region epilogue (block-uniform since ns1/ns2 are multiples of 128):
//   n0 <  ns1 : fp32 -> C0 (stride ns1)
//   n0 <  ns2 : bf16 split -> SHo/SLo (stride ns2-ns1)
//   else      : fp32 + bias -> C2 (stride N-ns2)
// ======================================================================
__global__ __launch_bounds__(256, 1)
void gemm2h(const __half* __restrict__ AHp,
            const __half* __restrict__ BHp, const __half* __restrict__ BLp,
            float* __restrict__ C0, __nv_bfloat16* __restrict__ SHo, __nv_bfloat16* __restrict__ SLo,
            float* __restrict__ C2, const float* __restrict__ bias,
            int M, int N, int K, int ns1, int ns2)
{
    extern __shared__ char smem[];
    const uint32_t sbase = smem_u32(smem);
    const int tid = threadIdx.x;
    const int wid = tid >> 5, lane = tid & 31;
    const int m0 = blockIdx.y * 128, n0 = blockIdx.x * 128;
    const int mw = (wid & 1) * 64, nw = (wid >> 1) * 32;
    const int TOT = K >> 6;

    float acc[4][4][4];
#pragma unroll
    for (int i = 0; i < 4; i++)
#pragma unroll
        for (int j = 0; j < 4; j++)
#pragma unroll
            for (int l = 0; l < 4; l++) acc[i][j][l] = 0.f;

    auto issue = [&](int it) {
        const int k0 = it << 6;
        const uint32_t st = sbase + (uint32_t)(it % 3) * 49152u;
#pragma unroll
        for (int l = 0; l < 4; l++) {
            int c = tid + (l << 8);
            int row = c >> 3;
            uint32_t dst = sw128((uint32_t)(row << 7) + ((c & 7) << 4));
            int el = (c & 7) << 3;
            size_t ao = (size_t)(m0 + row) * K + k0 + el;
            size_t bo = (size_t)(n0 + row) * K + k0 + el;
            cpasync16(st + dst,         AHp + ao);
            cpasync16(st + 16384 + dst, BHp + bo);
            cpasync16(st + 32768 + dst, BLp + bo);
        }
        asm volatile("cp.async.commit_group;" ::: "memory");
    };

    issue(0);
    if (TOT > 1) issue(1);
    for (int it = 0; it < TOT; it++) {
        if (it + 1 < TOT) {
            asm volatile("cp.async.wait_group 1;" ::: "memory");
        } else {
            asm volatile("cp.async.wait_group 0;" ::: "memory");
        }
        __syncthreads();
        const uint32_t st = sbase + (uint32_t)(it % 3) * 49152u;
#pragma unroll
        for (int ks = 0; ks < 4; ks++) {
            uint32_t afH[4][4], bfH[4][2], bfL[4][2];
#pragma unroll
            for (int mf = 0; mf < 4; mf++) {
                int row = mw + mf * 16 + (lane & 15);
                uint32_t bo = (uint32_t)(row << 7) + (uint32_t)(ks << 5) + ((lane >> 4) << 4);
                ldsm_x4(afH[mf], st + sw128(bo));
            }
#pragma unroll
            for (int half = 0; half < 2; half++) {
                int i2 = lane >> 3;
                int row = nw + half * 16 + ((i2 >> 1) << 3) + (lane & 7);
                uint32_t bo = (uint32_t)(row << 7) + (uint32_t)(ks << 5) + ((i2 & 1) << 4);
                uint32_t so = sw128(bo);
                uint32_t r[4];
                ldsm_x4(r, st + 16384 + so);
                bfH[half * 2][0] = r[0];     bfH[half * 2][1] = r[1];
                bfH[half * 2 + 1][0] = r[2]; bfH[half * 2 + 1][1] = r[3];
                ldsm_x4(r, st + 32768 + so);
                bfL[half * 2][0] = r[0];     bfL[half * 2][1] = r[1];
                bfL[half * 2 + 1][0] = r[2]; bfL[half * 2 + 1][1] = r[3];
            }
#pragma unroll
            for (int mf = 0; mf < 4; mf++)
#pragma unroll
                for (int nf = 0; nf < 4; nf++) {
                    mma16816h(acc[mf][nf], afH[mf], bfH[nf]);
                    mma16816h(acc[mf][nf], afH[mf], bfL[nf]);
                }
        }
        if (it + 2 < TOT) issue(it + 2);
    }

    const int rb = m0 + mw + (lane >> 2);
    const int cb = n0 + nw + ((lane & 3) << 1);
    const int region = (n0 < ns1) ? 0 : ((n0 < ns2) ? 1 : 2);
    const int w0 = ns1, w1 = ns2 - ns1, w2 = N - ns2;
#pragma unroll
    for (int mf = 0; mf < 4; mf++) {
#pragma unroll
        for (int half = 0; half < 2; half++) {
            int row = rb + mf * 16 + half * 8;
#pragma unroll
            for (int nf = 0; nf < 4; nf++) {
                int col = cb + nf * 8;
                float vx = acc[mf][nf][half * 2 + 0];
                float vy = acc[mf][nf][half * 2 + 1];
                if (region == 0) {
                    float2 v; v.x = vx; v.y = vy;
                    *(float2*)(C0 + (size_t)row * w0 + col) = v;
                } else if (region == 1) {
                    int cc = col - ns1;
                    __nv_bfloat16 h0 = __float2bfloat16(vx);
                    __nv_bfloat16 h1 = __float2bfloat16(vy);
                    __nv_bfloat16 l0 = __float2bfloat16(vx - __bfloat162float(h0));
                    __nv_bfloat16 l1 = __float2bfloat16(vy - __bfloat162float(h1));
                    *(__nv_bfloat162*)(SHo + (size_t)row * w1 + cc) = __nv_bfloat162(h0, h1);
                    *(__nv_bfloat162*)(SLo + (size_t)row * w1 + cc) = __nv_bfloat162(l0, l1);
                } else {
                    int cc = col - ns2;
                    vx += bias[cc]; vy += bias[cc + 1];
                    float2 v; v.x = vx; v.y = vy;
                    *(float2*)(C2 + (size_t)row * w2 + cc) = v;
                }
            }
        }
    }
}

// ======================================================================
// akernel (verified): A = qd @ kexp^T, tril, split to bf16.
// ======================================================================
__global__ __launch_bounds__(256, 1)
void akernel(const __nv_bfloat16* __restrict__ QH, const __nv_bfloat16* __restrict__ QL,
             const __nv_bfloat16* __restrict__ KH, const __nv_bfloat16* __restrict__ KL,
             __nv_bfloat16* __restrict__ AH, __nv_bfloat16* __restrict__ AL)
{
    extern __shared__ char smemc[];
    const uint32_t sb = smem_u32(smemc);
    const uint32_t oQH = 0, oQL = 32768, oKH = 65536, oKL = 98304;
    const int tid = threadIdx.x;
    const int wid = tid >> 5, lane = tid & 31;
    const int h = blockIdx.x, ch = blockIdx.y, bb = blockIdx.z;
    const int m0 = bb * TT + ch * CHUNK;
    const int colQ = h * 128;
    const size_t chA = (size_t)((bb * NCH + ch) * HH + h) * 16384;

#pragma unroll
    for (int l = 0; l < 8; l++) {
        int idx = tid + (l << 8);
        int row = idx >> 4, u = idx & 15;
        int kb = u >> 3, sub = u & 7;
        uint32_t dst = (uint32_t)kb * 16384u + sw128((uint32_t)(row << 7) + (sub << 4));
        size_t so = (size_t)(m0 + row) * DHALF + colQ + kb * 64 + sub * 8;
        cpasync16(sb + oQH + dst, QH + so);
        cpasync16(sb + oQL + dst, QL + so);
        cpasync16(sb + oKH + dst, KH + so);
        cpasync16(sb + oKL + dst, KL + so);
    }
    asm volatile("cp.async.commit_group;" ::: "memory");
    asm volatile("cp.async.wait_group 0;" ::: "memory");
    __syncthreads();

    const int mw = (wid & 1) * 64, nw = (wid >> 1) * 32;
    float acc[4][4][4];
#pragma unroll
    for (int i = 0; i < 4; i++)
#pragma unroll
        for (int j = 0; j < 4; j++)
#pragma unroll
            for (int l = 0; l < 4; l++) acc[i][j][l] = 0.f;

    mma_combo<4>(acc, sb + oQH, 16384, sb + oKH, 16384, mw, nw, lane);
    mma_combo<4>(acc, sb + oQH, 16384, sb + oKL, 16384, mw, nw, lane);
    mma_combo<4>(acc, sb + oQL, 16384, sb + oKH, 16384, mw, nw, lane);

#pragma unroll
    for (int mf = 0; mf < 4; mf++) {
#pragma unroll
        for (int half = 0; half < 2; half++) {
            int i = mw + mf * 16 + half * 8 + (lane >> 2);
#pragma unroll
            for (int nf = 0; nf < 4; nf++) {
                int j = nw + nf * 8 + ((lane & 3) << 1);
                float v0 = (j     <= i) ? acc[mf][nf][half * 2 + 0] : 0.f;
                float v1 = (j + 1 <= i) ? acc[mf][nf][half * 2 + 1] : 0.f;
                __nv_bfloat16 h0 = __float2bfloat16(v0);
                __nv_bfloat16 h1 = __float2bfloat16(v1);
                __nv_bfloat16 l0 = __float2bfloat16(v0 - __bfloat162float(h0));
                __nv_bfloat16 l1 = __float2bfloat16(v1 - __bfloat162float(h1));
                size_t oi = chA + (size_t)i * 128 + j;
                *(__nv_bfloat162*)(AH + oi) = __nv_bfloat162(h0, h1);
                *(__nv_bfloat162*)(AL + oi) = __nv_bfloat162(l0, l1);
            }
        }
    }
}

// ======================================================================
// phase1: 96KB smem (2 CTA/SM). o = tril(A)@v -> O first (A 64K + vT 32K),
// then kdT overwrites the A region and U = kd^T@v -> U blob.
// ======================================================================
__global__ __launch_bounds__(256, 1)
void phase1_kernel(const __nv_bfloat16* __restrict__ AH, const __nv_bfloat16* __restrict__ AL,
                   const __nv_bfloat16* __restrict__ KDH, const __nv_bfloat16* __restrict__ KDL,
                   const __nv_bfloat16* __restrict__ VH, const __nv_bfloat16* __restrict__ VL,
                   float* __restrict__ O, float* __restrict__ U)
{
    extern __shared__ char smemc[];
    const uint32_t sb = smem_u32(smemc);
    const uint32_t oA = 0, oAl = 32768, oVH = 65536, oVL = 81920;  // 96K

    const int tid = threadIdx.x;
    const int wid = tid >> 5, lane = tid & 31;
    const int ch = blockIdx.x >> 2, vsl = blockIdx.x & 3;
    const int h = blockIdx.y, bb = blockIdx.z;
    const int m0 = bb * TT + ch * CHUNK;
    const int colQ = h * 128;
    const int colV = h * 256 + vsl * 64;
    const size_t chA = (size_t)((bb * NCH + ch) * HH + h) * 16384;
    const size_t ublob = (size_t)(((bb * HH + h) * 4 + vsl) * NCH + ch) * 8192;
    const int mw = (wid & 3) * 32, nw = (wid >> 2) * 32;

    // A tiles via cp.async
#pragma unroll
    for (int l = 0; l < 8; l++) {
        int idx = tid + (l << 8);
        int row = idx >> 4, u = idx & 15;
        int kb = u >> 3, sub = u & 7;
        uint32_t dst = (uint32_t)kb * 16384u + sw128((uint32_t)(row << 7) + (sub << 4));
        size_t sa = chA + (size_t)row * 128 + kb * 64 + sub * 8;
        cpasync16(sb + oA  + dst, AH + sa);
        cpasync16(sb + oAl + dst, AL + sa);
    }
    asm volatile("cp.async.commit_group;" ::: "memory");

    // vT transpose: [j][n] -> [n][j]
#pragma unroll
    for (int l = 0; l < 16; l++) {
        int idx = tid + (l << 8);
        int j = idx >> 5, n = (idx & 31) << 1;
        uint32_t wv = *(const uint32_t*)(VH + (size_t)(m0 + j) * DD + colV + n);
        uint32_t wl = *(const uint32_t*)(VL + (size_t)(m0 + j) * DD + colV + n);
        uint32_t kbo = (uint32_t)(j >> 6) * 8192u;
        uint32_t off0 = kbo + sw128((uint32_t)(n << 7) + ((j & 63) << 1));
        uint32_t off1 = kbo + sw128((uint32_t)((n + 1) << 7) + ((j & 63) << 1));
        *(unsigned short*)(smemc + oVH + off0) = (unsigned short)(wv & 0xffff);
        *(unsigned short*)(smemc + oVH + off1) = (unsigned short)(wv >> 16);
        *(unsigned short*)(smemc + oVL + off0) = (unsigned short)(wl & 0xffff);
        *(unsigned short*)(smemc + oVL + off1) = (unsigned short)(wl >> 16);
    }
    asm volatile("cp.async.wait_group 0;" ::: "memory");
    __syncthreads();

    // o = tril(A)@v
    float acc[2][4][4];
#pragma unroll
    for (int i = 0; i < 2; i++)
#pragma unroll
        for (int j = 0; j < 4; j++)
#pragma unroll
            for (int l = 0; l < 4; l++) acc[i][j][l] = 0.f;
    mma_combo<2>(acc, sb + oA,  16384, sb + oVH, 8192, mw, nw, lane);
    mma_combo<2>(acc, sb + oA,  16384, sb + oVL, 8192, mw, nw, lane);
    mma_combo<2>(acc, sb + oAl, 16384, sb + oVH, 8192, mw, nw, lane);
#pragma unroll
    for (int mf = 0; mf < 2; mf++) {
#pragma unroll
        for (int half = 0; half < 2; half++) {
            int row = m0 + mw + mf * 16 + half * 8 + (lane >> 2);
#pragma unroll
            for (int nf = 0; nf < 4; nf++) {
                int col = colV + nw + nf * 8 + ((lane & 3) << 1);
                float2 v;
                v.x = acc[mf][nf][half * 2 + 0];
                v.y = acc[mf][nf][half * 2 + 1];
                *(float2*)&O[(size_t)row * DD + col] = v;
            }
        }
    }
    __syncthreads();   // A reads done -> safe to overwrite

    // kdT transpose into the A region: [j][d] -> [d][j]
#pragma unroll
    for (int l = 0; l < 32; l++) {
        int idx = tid + (l << 8);
        int j = idx >> 6, d = (idx & 63) << 1;
        uint32_t wv = *(const uint32_t*)(KDH + (size_t)(m0 + j) * DHALF + colQ + d);
        uint32_t wl = *(const uint32_t*)(KDL + (size_t)(m0 + j) * DHALF + colQ + d);
        uint32_t kbo = (uint32_t)(j >> 6) * 16384u;
        uint32_t off0 = kbo + sw128((uint32_t)(d << 7) + ((j & 63) << 1));
        uint32_t off1 = kbo + sw128((uint32_t)((d + 1) << 7) + ((j & 63) << 1));
        *(unsigned short*)(smemc + oA  + off0) = (unsigned short)(wv & 0xffff);
        *(unsigned short*)(smemc + oA  + off1) = (unsigned short)(wv >> 16);
        *(unsigned short*)(smemc + oAl + off0) = (unsigned short)(wl & 0xffff);
        *(unsigned short*)(smemc + oAl + off1) = (unsigned short)(wl >> 16);
    }
    __syncthreads();

    // U = kd^T @ v
    float uacc[2][4][4];
#pragma unroll
    for (int i = 0; i < 2; i++)
#pragma unroll
        for (int j = 0; j < 4; j++)
#pragma unroll
            for (int l = 0; l < 4; l++) uacc[i][j][l] = 0.f;
    mma_combo<2>(uacc, sb + oA,  16384, sb + oVH, 8192, mw, nw, lane);
    mma_combo<2>(uacc, sb + oA,  16384, sb + oVL, 8192, mw, nw, lane);
    mma_combo<2>(uacc, sb + oAl, 16384, sb + oVH, 8192, mw, nw, lane);
#pragma unroll
    for (int mf = 0; mf < 2; mf++) {
#pragma unroll
        for (int half = 0; half < 2; half++) {
            int d = mw + mf * 16 + half * 8 + (lane >> 2);
            uint32_t kb = (uint32_t)(d >> 6) * 4096u;
            uint32_t d2b = (uint32_t)((d & 63) << 1);
#pragma unroll
            for (int nf = 0; nf < 4; nf++) {
                int n = nw + nf * 8 + ((lane & 3) << 1);
                uint32_t i0 = kb + (sw128(((uint32_t)n << 7) + d2b) >> 1);
                uint32_t i1 = kb + (sw128(((uint32_t)(n + 1) << 7) + d2b) >> 1);
                U[ublob + i0] = uacc[mf][nf][half * 2 + 0];
                U[ublob + i1] = uacc[mf][nf][half * 2 + 1];
            }
        }
    }
}

// ======================================================================
// scan (verified R11)
// ======================================================================
__global__ __launch_bounds__(256, 1)
void scan_kernel(const float* __restrict__ U, const float* __restrict__ DEC,
                 __nv_bfloat16* __restrict__ SBH, __nv_bfloat16* __restrict__ SBL)
{
    __shared__ float sdec[128];
    const int t = threadIdx.x;
    const int vsl = blockIdx.x, h = blockIdx.y, bb = blockIdx.z;
    const int blobbase = ((bb * HH + h) * 4 + vsl) * NCH;
    const int colQ = h * 128;

    int dbase[8];
#pragma unroll
    for (int g = 0; g < 8; g++) {
        uint32_t ibase = (uint32_t)(t + g * 256) * 4;
        uint32_t braw = sw128((ibase & 4095) * 2);
        dbase[g] = (int)(ibase >> 12) * 64 + (int)((braw & 127) >> 1);
    }

    float S[32];
#pragma unroll
    for (int i = 0; i < 32; i++) S[i] = 0.f;

    for (int ch = 0; ch < NCH; ch++) {
        if (t < 128) sdec[t] = DEC[(size_t)(bb * NCH + ch) * DHALF + colQ + t];
        const size_t blob = (size_t)(blobbase + ch) * 8192;
#pragma unroll
        for (int g = 0; g < 8; g++) {
            uint32_t ibase = (uint32_t)(t + g * 256) * 4;
            float v0 = S[g * 4 + 0], v1 = S[g * 4 + 1], v2 = S[g * 4 + 2], v3 = S[g * 4 + 3];
            __nv_bfloat16 h0 = __float2bfloat16(v0), h1 = __float2bfloat16(v1);
            __nv_bfloat16 h2 = __float2bfloat16(v2), h3 = __float2bfloat16(v3);
            *(__nv_bfloat162*)(SBH + blob + ibase)     = __nv_bfloat162(h0, h1);
            *(__nv_bfloat162*)(SBH + blob + ibase + 2) = __nv_bfloat162(h2, h3);
            __nv_bfloat16 l0 = __float2bfloat16(v0 - __bfloat162float(h0));
            __nv_bfloat16 l1 = __float2bfloat16(v1 - __bfloat162float(h1));
            __nv_bfloat16 l2 = __float2bfloat16(v2 - __bfloat162float(h2));
            __nv_bfloat16 l3 = __float2bfloat16(v3 - __bfloat162float(h3));
            *(__nv_bfloat162*)(SBL + blob + ibase)     = __nv_bfloat162(l0, l1);
            *(__nv_bfloat162*)(SBL + blob + ibase + 2) = __nv_bfloat162(l2, l3);
        }
        __syncthreads();
#pragma unroll
        for (int g = 0; g < 8; g++) {
            uint32_t ibase = (uint32_t)(t + g * 256) * 4;
            float4 u = *(const float4*)(U + blob + ibase);
            int d0 = dbase[g];
            S[g * 4 + 0] = sdec[d0 + 0] * S[g * 4 + 0] + u.x;
            S[g * 4 + 1] = sdec[d0 + 1] * S[g * 4 + 1] + u.y;
            S[g * 4 + 2] = sdec[d0 + 2] * S[g * 4 + 2] + u.z;
            S[g * 4 + 3] = sdec[d0 + 3] * S[g * 4 + 3] + u.w;
        }
        __syncthreads();
    }
}

// ======================================================================
// o2 (verified R11): O += qd @ S_ch
// ======================================================================
__global__ __launch_bounds__(256, 1)
void o2_kernel(const __nv_bfloat16* __restrict__ QH, const __nv_bfloat16* __restrict__ QL,
               const __nv_bfloat16* __restrict__ SBH, const __nv_bfloat16* __restrict__ SBL,
               float* __restrict__ O)
{
    extern __shared__ char smemc[];
    const uint32_t sb = smem_u32(smemc);
    const uint32_t oQH = 0, oQL = 32768, oSH = 65536, oSL = 81920;

    const int tid = threadIdx.x;
    const int wid = tid >> 5, lane = tid & 31;
    const int ch = blockIdx.x >> 2, vsl = blockIdx.x & 3;
    const int h = blockIdx.y, bb = blockIdx.z;
    const int m0 = bb * TT + ch * CHUNK;
    const int colQ = h * 128;
    const int colV = h * 256 + vsl * 64;
    const size_t blob = (size_t)(((bb * HH + h) * 4 + vsl) * NCH + ch) * 8192;
    const int mw = (wid & 3) * 32, nw = (wid >> 2) * 32;

#pragma unroll
    for (int l = 0; l < 8; l++) {
        int idx = tid + (l << 8);
        int row = idx >> 4, u = idx & 15;
        int kb = u >> 3, sub = u & 7;
        uint32_t dst = (uint32_t)kb * 16384u + sw128((uint32_t)(row << 7) + (sub << 4));
        size_t so = (size_t)(m0 + row) * DHALF + colQ + kb * 64 + sub * 8;
        cpasync16(sb + oQH + dst, QH + so);
        cpasync16(sb + oQL + dst, QL + so);
    }
#pragma unroll
    for (int l = 0; l < 4; l++) {
        int i = tid + (l << 8);
        cpasync16(sb + oSH + (i << 4), SBH + blob + (size_t)i * 8);
        cpasync16(sb + oSL + (i << 4), SBL + blob + (size_t)i * 8);
    }
    asm volatile("cp.async.commit_group;" ::: "memory");
    asm volatile("cp.async.wait_group 0;" ::: "memory");
    __syncthreads();

    float acc[2][4][4];
#pragma unroll
    for (int i = 0; i < 2; i++)
#pragma unroll
        for (int j = 0; j < 4; j++)
#pragma unroll
            for (int l = 0; l < 4; l++) acc[i][j][l] = 0.f;

    mma_combo<2>(acc, sb + oQH, 16384, sb + oSH, 8192, mw, nw, lane);
    mma_combo<2>(acc, sb + oQH, 16384, sb + oSL, 8192, mw, nw, lane);
    mma_combo<2>(acc, sb + oQL, 16384, sb + oSH, 8192, mw, nw, lane);

#pragma unroll
    for (int mf = 0; mf < 2; mf++) {
#pragma unroll
        for (int half = 0; half < 2; half++) {
            int row = m0 + mw + mf * 16 + half * 8 + (lane >> 2);
#pragma unroll
            for (int nf = 0; nf < 4; nf++) {
                int col = colV + nw + nf * 8 + ((lane & 3) << 1);
                float2 v = *(float2*)&O[(size_t)row * DD + col];
                v.x += acc[mf][nf][half * 2 + 0];
                v.y += acc[mf][nf][half * 2 + 1];
                *(float2*)&O[(size_t)row * DD + col] = v;
            }
        }
    }
}

// ======================================================================
// x -> fp16
// ======================================================================
__global__ void xhalf(const float4* __restrict__ X, __half* __restrict__ H, int n4)
{
    int i = blockIdx.x * blockDim.x + threadIdx.x;
    if (i >= n4) return;
    float4 v = X[i];
    __half2* Hp = (__half2*)H;
    Hp[i * 2]     = __floats2half2_rn(v.x, v.y);
    Hp[i * 2 + 1] = __floats2half2_rn(v.z, v.w);
}

// ======================================================================
// transpose W -> combined WT fp16 hi/lo
// ======================================================================
__global__ void wsplit_t(const float* __restrict__ W, __half* __restrict__ Th,
                         __half* __restrict__ Tl, int K, int N, int rowoff, float alpha)
{
    __shared__ float t[32][33];
    const int n0 = blockIdx.x * 32, k0 = blockIdx.y * 32;
    const int tx = threadIdx.x, ty = threadIdx.y;
#pragma unroll
    for (int i = 0; i < 4; i++) {
        int k = ty + i * 8;
        t[k][tx] = W[(size_t)(k0 + k) * N + n0 + tx];
    }
    __syncthreads();
#pragma unroll
    for (int i = 0; i < 4; i++) {
        int n = ty + i * 8;
        float v = t[tx][n] * alpha;
        __half h = __float2half(v);
        size_t oi = (size_t)(rowoff + n0 + n) * K + k0 + tx;
        Th[oi] = h;
        Tl[oi] = __float2half(v - __half2float(h));
    }
}

// ======================================================================
// kg1
// ======================================================================
__global__ void kg1_kernel(const float* __restrict__ x, const float* __restrict__ W1,
                           float* __restrict__ out)
{
    const int wid = threadIdx.x >> 5, lane = threadIdx.x & 31;
    const int row = blockIdx.x * 8 + wid;
    const float* xp = x + (size_t)row * DD;
    float acc[16];
#pragma unroll
    for (int c = 0; c < 16; c++) acc[c] = 0.f;
    for (int k = lane; k < DD; k += 32) {
        float xv = xp[k];
        const float4* wp = (const float4*)(W1 + (size_t)k * 16);
        float4 w0 = wp[0], w1 = wp[1], w2 = wp[2], w3 = wp[3];
        acc[0]  += xv * w0.x; acc[1]  += xv * w0.y; acc[2]  += xv * w0.z; acc[3]  += xv * w0.w;
        acc[4]  += xv * w1.x; acc[5]  += xv * w1.y; acc[6]  += xv * w1.z; acc[7]  += xv * w1.w;
        acc[8]  += xv * w2.x; acc[9]  += xv * w2.y; acc[10] += xv * w2.z; acc[11] += xv * w2.w;
        acc[12] += xv * w3.x; acc[13] += xv * w3.y; acc[14] += xv * w3.z; acc[15] += xv * w3.w;
    }
#pragma unroll
    for (int c = 0; c < 16; c++) {
        float v = acc[c];
#pragma unroll
        for (int off = 16; off; off >>= 1) v += __shfl_xor_sync(0xFFFFFFFFu, v, off);
        if (lane == 0) out[(size_t)row * 16 + c] = v;
    }
}

// ======================================================================
// gk
// ======================================================================
__global__ void gk_kernel(const float* __restrict__ KG1,
                          const float* __restrict__ W2,
                          const float* __restrict__ b2,
                          float* __restrict__ GK)
{
    __shared__ float a[16];
    int m = blockIdx.x;
    if (threadIdx.x < 16) a[threadIdx.x] = KG1[(size_t)m * 16 + threadIdx.x];
    __syncthreads();
    for (int c = threadIdx.x; c < DHALF; c += 128) {
        float z = b2[c];
#pragma unroll
        for (int r = 0; r < 16; r++) z = fmaf(a[r], W2[(size_t)r * DHALF + c], z);
        float e = __expf(-fabsf(z));
        float l = __logf(1.f + e);
        float ls = (z >= 0.f) ? -l : (z - l);
        GK[(size_t)m * DHALF + c] = ls * INV_NORM_GK;
    }
}

// ======================================================================
// prep
// ======================================================================
__global__ void prep_kernel(const float* __restrict__ QK,
                            const float* __restrict__ GK,
                            __nv_bfloat16* __restrict__ QHo, __nv_bfloat16* __restrict__ QLo,
                            __nv_bfloat16* __restrict__ KHo, __nv_bfloat16* __restrict__ KLo,
                            __nv_bfloat16* __restrict__ KDHo, __nv_bfloat16* __restrict__ KDLo,
                            float* __restrict__ DEC)
{
    int g = blockIdx.x * blockDim.x + threadIdx.x;
    int col = g & (DHALF - 1);
    int bc  = g >> 10;
    int row0 = ((bc >> 4) * TT) + ((bc & 15) * CHUNK);
    size_t baseg = (size_t)row0 * DHALF + col;
    size_t baseq = (size_t)row0 * 2048 + col;

    float gs = 0.f;
#pragma unroll 4
    for (int i = 0; i < CHUNK; i++) gs += GK[baseg + (size_t)i * DHALF];
    float egs = __expf(gs);

    float gc = 0.f;
    for (int i = 0; i < CHUNK; i++) {
        size_t idx = baseg + (size_t)i * DHALF;
        size_t qdx = baseq + (size_t)i * 2048;
        gc += GK[idx];
        float eg = __expf(gc);
        float qd = QK[qdx] * eg;
        float kv = QK[qdx + 1024];
        float ke = __fdividef(kv, eg);
        float kd = ke * egs;
        __nv_bfloat16 qh = __float2bfloat16(qd);
        __nv_bfloat16 kh = __float2bfloat16(ke);
        __nv_bfloat16 dh = __float2bfloat16(kd);
        QHo[idx]  = qh; QLo[idx]  = __float2bfloat16(qd - __bfloat162float(qh));
        KHo[idx]  = kh; KLo[idx]  = __float2bfloat16(ke - __bfloat162float(kh));
        KDHo[idx] = dh; KDLo[idx] = __float2bfloat16(kd - __bfloat162float(dh));
    }
    DEC[(size_t)bc * DHALF + col] = egs;
}

// ======================================================================
// norm * silu -> fp16
// ======================================================================
__global__ void norm_gate_kernel(const float* __restrict__ O,
                                 const float* __restrict__ G,
                                 __half* __restrict__ PH)
{
    int m = blockIdx.x, h = blockIdx.y;
    int tid = threadIdx.x;
    size_t idx = (size_t)m * DD + h * DV + tid;
    float v = O[idx];
    float s = v, s2 = v * v;
#pragma unroll
    for (int off = 16; off; off >>= 1) {
        s  += __shfl_xor_sync(0xFFFFFFFFu, s,  off);
        s2 += __shfl_xor_sync(0xFFFFFFFFu, s2, off);
    }
    __shared__ float ws[8], ws2[8];
    int w = tid >> 5, l = tid & 31;
    if (l == 0) { ws[w] = s; ws2[w] = s2; }
    __syncthreads();
    float ts = 0.f, ts2 = 0.f;
#pragma unroll
    for (int i = 0; i < 8; i++) { ts += ws[i]; ts2 += ws2[i]; }
    float mu = ts * (1.f / 256.f);
    float var = ts2 * (1.f / 256.f) - mu * mu;
    float nv = (v - mu) * rsqrtf(var + 1e-5f);
    float gt = G[idx];
    float sg = gt / (1.f + __expf(-gt));
    PH[idx] = __float2half(sg * nv);
}

// ======================================================================
extern "C" void kernel_launch(void* const* d_in, const int* in_sizes, int n_in,
                              void* d_out, int out_size)
{
    const float* x    = (const float*)d_in[0];
    const float* Wq   = (const float*)d_in[1];
    const float* Wk   = (const float*)d_in[2];
    const float* Wkg1 = (const float*)d_in[3];
    const float* Wkg2 = (const float*)d_in[4];
    const float* bkg2 = (const float*)d_in[5];
    const float* Wv   = (const float*)d_in[6];
    const float* Wg   = (const float*)d_in[7];
    const float* bg   = (const float*)d_in[8];
    const float* Wo   = (const float*)d_in[9];
    float* out = (float*)d_out;

    float *pQK, *pGK, *pKG1, *pDEC, *pG, *pO, *pU;
    __half *pXH, *pWTH, *pWTL, *pPH;
    __nv_bfloat16 *pQH, *pQL, *pKH, *pKL, *pKDH, *pKDL, *pVH, *pVL, *pAH, *pAL, *pSBH, *pSBL;
    cudaGetSymbolAddress((void**)&pQK,  g_QK);
    cudaGetSymbolAddress((void**)&pGK,  g_GK);
    cudaGetSymbolAddress((void**)&pKG1, g_KG1);
    cudaGetSymbolAddress((void**)&pDEC, g_DEC);
    cudaGetSymbolAddress((void**)&pG,   g_G);
    cudaGetSymbolAddress((void**)&pO,   g_O);
    cudaGetSymbolAddress((void**)&pU,   g_U);
    cudaGetSymbolAddress((void**)&pXH,  g_XH);
    cudaGetSymbolAddress((void**)&pWTH, g_WTH);
    cudaGetSymbolAddress((void**)&pWTL, g_WTL);
    cudaGetSymbolAddress((void**)&pPH,  g_PH);
    cudaGetSymbolAddress((void**)&pQH,  g_QH);
    cudaGetSymbolAddress((void**)&pQL,  g_QL);
    cudaGetSymbolAddress((void**)&pKH,  g_KH);
    cudaGetSymbolAddress((void**)&pKL,  g_KL);
    cudaGetSymbolAddress((void**)&pKDH, g_KDH);
    cudaGetSymbolAddress((void**)&pKDL, g_KDL);
    cudaGetSymbolAddress((void**)&pVH,  g_VH);
    cudaGetSymbolAddress((void**)&pVL,  g_VL);
    cudaGetSymbolAddress((void**)&pAH,  g_AH);
    cudaGetSymbolAddress((void**)&pAL,  g_AL);
    cudaGetSymbolAddress((void**)&pSBH, g_SBH);
    cudaGetSymbolAddress((void**)&pSBL, g_SBL);

    cudaFuncSetAttribute(gemm2h,        cudaFuncAttributeMaxDynamicSharedMemorySize, 147456);
    cudaFuncSetAttribute(akernel,       cudaFuncAttributeMaxDynamicSharedMemorySize, 131072);
    cudaFuncSetAttribute(phase1_kernel, cudaFuncAttributeMaxDynamicSharedMemorySize, 98304);
    cudaFuncSetAttribute(o2_kernel,     cudaFuncAttributeMaxDynamicSharedMemorySize, 98304);

    dim3 tb(32, 8);
    int n4 = MROWS * DD / 4;

    // x -> fp16 ; weights -> combined WT fp16 hi/lo (Q|K*scale|V|G|O)
    xhalf<<<(n4 + 255) / 256, 256>>>((const float4*)x, pXH, n4);
    kg1_kernel<<<MROWS / 8, 256>>>(x, Wkg1, pKG1);
    wsplit_t<<<dim3(DHALF / 32, DD / 32), tb>>>(Wq, pWTH, pWTL, DD, DHALF, 0, 1.0f);
    wsplit_t<<<dim3(DHALF / 32, DD / 32), tb>>>(Wk, pWTH, pWTL, DD, DHALF, 1024, SCALING);
    wsplit_t<<<dim3(DD / 32, DD / 32), tb>>>(Wv, pWTH, pWTL, DD, DD, 2048, 1.0f);
    wsplit_t<<<dim3(DD / 32, DD / 32), tb>>>(Wg, pWTH, pWTL, DD, DD, 4096, 1.0f);
    wsplit_t<<<dim3(DD / 32, DD / 32), tb>>>(Wo, pWTH, pWTL, DD, DD, 6144, 1.0f);

    // fused Q+K+V+G projection (N=6144): QK fp32 | V bf16-split | G fp32+bias
    gemm2h<<<dim3(6144 / 128, MROWS / 128), 256, 147456>>>(pXH, pWTH, pWTL,
        pQK, pVH, pVL, pG, bg, MROWS, 6144, DD, 2048, 4096);

    // gk + decay precompute
    gk_kernel<<<MROWS, 128>>>(pKG1, Wkg2, bkg2, pGK);
    prep_kernel<<<256, 256>>>(pQK, pGK, pQH, pQL, pKH, pKL, pKDH, pKDL, pDEC);

    // A chunks
    akernel<<<dim3(HH, NCH, BB), 256, 131072>>>(pQH, pQL, pKH, pKL, pAH, pAL);

    // parallel: O_intra + U chunks (96K smem, 2 CTA/SM)
    phase1_kernel<<<dim3(NCH * 4, HH, BB), 256, 98304>>>(pAH, pAL, pKDH, pKDL,
                                                         pVH, pVL, pO, pU);
    // fast elementwise scan -> S blobs
    scan_kernel<<<dim3(4, HH, BB), 256>>>(pU, pDEC, pSBH, pSBL);
    // parallel: O += qd @ S
    o2_kernel<<<dim3(NCH * 4, HH, BB), 256, 98304>>>(pQH, pQL, pSBH, pSBL, pO);

    // groupnorm + silu gate -> fp16
    norm_gate_kernel<<<dim3(MROWS, HH), 256>>>(pO, pG, pPH);

    // output projection (fp32 out, region0 only)
    gemm2h<<<dim3(2048 / 128, MROWS / 128), 256, 147456>>>(pPH,
        pWTH + (size_t)6144 * DD, pWTL + (size_t)6144 * DD,
        out, nullptr, nullptr, nullptr, nullptr, MROWS, 2048, DD, 2048, 2048);
}

// round 15
// speedup vs baseline: 1.1670x; 1.1082x over previous
#include <cuda_runtime.h>
#include <cuda_bf16.h>
#include <cuda_fp16.h>
#include <math.h>
#include <stdint.h>

// ---------------- problem constants ----------------
#define BB     4
#define TT     2048
#define DD     2048
#define HH     8
#define DK     128
#define DV     256
#define CHUNK  128
#define NCH    16
#define MROWS  (BB*TT)      // 8192
#define DHALF  (DD/2)       // 1024
#define SCALING 0.0625f
#define INV_NORM_GK (1.0f/16.0f)
#define NCHUNKS (BB*NCH*HH) // 512
#define NBLOBS  (BB*HH*4*NCH) // 2048
#define WTROWS 8192

// ---------------- scratch ----------------
__device__ float g_QK [(size_t)MROWS * 2048];
__device__ float g_GK [(size_t)MROWS * DHALF];
__device__ float g_KG1[(size_t)MROWS * 16];
__device__ float g_DEC[(size_t)BB * NCH * DHALF];
__device__ float g_G  [(size_t)MROWS * DD];
__device__ float g_O  [(size_t)MROWS * DD];
__device__ float g_U  [(size_t)NBLOBS * 8192];
__device__ __half g_XH [(size_t)MROWS * DD];
__device__ __half g_WTH[(size_t)WTROWS * DD];
__device__ __half g_WTL[(size_t)WTROWS * DD];
__device__ __half g_PH [(size_t)MROWS * DD];
__device__ __nv_bfloat16 g_QH [(size_t)MROWS * DHALF];
__device__ __nv_bfloat16 g_QL [(size_t)MROWS * DHALF];
__device__ __nv_bfloat16 g_KH [(size_t)MROWS * DHALF];
__device__ __nv_bfloat16 g_KL [(size_t)MROWS * DHALF];
__device__ __nv_bfloat16 g_KDH[(size_t)MROWS * DHALF];
__device__ __nv_bfloat16 g_KDL[(size_t)MROWS * DHALF];
__device__ __nv_bfloat16 g_VH [(size_t)MROWS * DD];
__device__ __nv_bfloat16 g_VL [(size_t)MROWS * DD];
__device__ __nv_bfloat16 g_AH [(size_t)NCHUNKS * CHUNK * CHUNK];
__device__ __nv_bfloat16 g_AL [(size_t)NCHUNKS * CHUNK * CHUNK];
__device__ __nv_bfloat16 g_SBH[(size_t)NBLOBS * 64 * 128];
__device__ __nv_bfloat16 g_SBL[(size_t)NBLOBS * 64 * 128];

// ================= helpers =================
__device__ __forceinline__ uint32_t smem_u32(const void* p) {
    uint32_t a;
    asm("{ .reg .u64 t; cvta.to.shared.u64 t, %1; cvt.u32.u64 %0, t; }" : "=r"(a) : "l"(p));
    return a;
}
__device__ __forceinline__ void cpasync16(uint32_t dst, const void* src) {
    asm volatile("cp.async.cg.shared.global [%0], [%1], 16;" :: "r"(dst), "l"(src) : "memory");
}
__device__ __forceinline__ void ldsm_x4(uint32_t* r, uint32_t addr) {
    asm volatile("ldmatrix.sync.aligned.m8n8.x4.shared.b16 {%0,%1,%2,%3}, [%4];"
                 : "=r"(r[0]), "=r"(r[1]), "=r"(r[2]), "=r"(r[3]) : "r"(addr));
}
__device__ __forceinline__ void mma16816(float* c, const uint32_t* a, const uint32_t* b) {
    asm volatile(
        "mma.sync.aligned.m16n8k16.row.col.f32.bf16.bf16.f32 "
        "{%0,%1,%2,%3}, {%4,%5,%6,%7}, {%8,%9}, {%0,%1,%2,%3};"
        : "+f"(c[0]), "+f"(c[1]), "+f"(c[2]), "+f"(c[3])
        : "r"(a[0]), "r"(a[1]), "r"(a[2]), "r"(a[3]), "r"(b[0]), "r"(b[1]));
}
__device__ __forceinline__ void mma16816h(float* c, const uint32_t* a, const uint32_t* b) {
    asm volatile(
        "mma.sync.aligned.m16n8k16.row.col.f32.f16.f16.f32 "
        "{%0,%1,%2,%3}, {%4,%5,%6,%7}, {%8,%9}, {%0,%1,%2,%3};"
        : "+f"(c[0]), "+f"(c[1]), "+f"(c[2]), "+f"(c[3])
        : "r"(a[0]), "r"(a[1]), "r"(a[2]), "r"(a[3]), "r"(b[0]), "r"(b[1]));
}
static __device__ __forceinline__ uint32_t sw128(uint32_t o) { return o ^ ((o >> 3) & 0x70); }

// acc[MF][4][4] += A_tile @ B_tile^T over K=128 (2 sw128 K-subtiles) [bf16]
template<int MF>
__device__ __forceinline__ void mma_combo(float (*acc)[4][4], uint32_t Ab, uint32_t abs_,
                                          uint32_t Bb, uint32_t bbs, int mw, int nw, int lane)
{
#pragma unroll
    for (int kb = 0; kb < 2; kb++) {
#pragma unroll
        for (int ks = 0; ks < 4; ks++) {
            uint32_t af[MF][4];
#pragma unroll
            for (int mf = 0; mf < MF; mf++) {
                int row = mw + mf * 16 + (lane & 15);
                uint32_t bo = (uint32_t)(row << 7) + (uint32_t)(ks << 5) + ((lane >> 4) << 4);
                ldsm_x4(af[mf], Ab + kb * abs_ + sw128(bo));
            }
            uint32_t bfr[4][2];
#pragma unroll
            for (int half = 0; half < 2; half++) {
                int i2 = lane >> 3;
                int row = nw + half * 16 + ((i2 >> 1) << 3) + (lane & 7);
                uint32_t bo = (uint32_t)(row << 7) + (uint32_t)(ks << 5) + ((i2 & 1) << 4);
                uint32_t r[4];
                ldsm_x4(r, Bb + kb * bbs + sw128(bo));
                bfr[half * 2][0] = r[0];     bfr[half * 2][1] = r[1];
                bfr[half * 2 + 1][0] = r[2]; bfr[half * 2 + 1][1] = r[3];
            }
#pragma unroll
            for (int mf = 0; mf < MF; mf++)
#pragma unroll
                for (int nf = 0; nf < 4; nf++)
                    mma16816(acc[mf][nf], af[mf], bfr[nf]);
        }
    }
}

// ======================================================================
// gemm2h: fp16 GEMM (128x128, 3-stage, 256 thr). Blocks with n0 < np1 do
// 2-pass (Bh+Bl); blocks with n0 >= np1 do 1-pass (Bh only, skip BL load).
// 3-region epilogue (block-uniform; ns1/ns2 multiples of 128):
//   n0 <  ns1 : fp32 -> C0 (stride ns1)
//   n0 <  ns2 : bf16 split -> SHo/SLo (stride ns2-ns1)
//   else      : fp32 + bias -> C2 (stride N-ns2)
// ======================================================================
__global__ __launch_bounds__(256, 1)
void gemm2h(const __half* __restrict__ AHp,
            const __half* __restrict__ BHp, const __half* __restrict__ BLp,
            float* __restrict__ C0, __nv_bfloat16* __restrict__ SHo, __nv_bfloat16* __restrict__ SLo,
            float* __restrict__ C2, const float* __restrict__ bias,
            int M, int N, int K, int ns1, int ns2, int np1)
{
    extern __shared__ char smem[];
    const uint32_t sbase = smem_u32(smem);
    const int tid = threadIdx.x;
    const int wid = tid >> 5, lane = tid & 31;
    const int m0 = blockIdx.y * 128, n0 = blockIdx.x * 128;
    const int mw = (wid & 1) * 64, nw = (wid >> 1) * 32;
    const int TOT = K >> 6;
    const bool twopass = (n0 < np1);

    float acc[4][4][4];
#pragma unroll
    for (int i = 0; i < 4; i++)
#pragma unroll
        for (int j = 0; j < 4; j++)
#pragma unroll
            for (int l = 0; l < 4; l++) acc[i][j][l] = 0.f;

    auto issue = [&](int it) {
        const int k0 = it << 6;
        const uint32_t st = sbase + (uint32_t)(it % 3) * 49152u;
#pragma unroll
        for (int l = 0; l < 4; l++) {
            int c = tid + (l << 8);
            int row = c >> 3;
            uint32_t dst = sw128((uint32_t)(row << 7) + ((c & 7) << 4));
            int el = (c & 7) << 3;
            size_t ao = (size_t)(m0 + row) * K + k0 + el;
            size_t bo = (size_t)(n0 + row) * K + k0 + el;
            cpasync16(st + dst,         AHp + ao);
            cpasync16(st + 16384 + dst, BHp + bo);
            if (twopass) cpasync16(st + 32768 + dst, BLp + bo);
        }
        asm volatile("cp.async.commit_group;" ::: "memory");
    };

    issue(0);
    if (TOT > 1) issue(1);
    for (int it = 0; it < TOT; it++) {
        if (it + 1 < TOT) {
            asm volatile("cp.async.wait_group 1;" ::: "memory");
        } else {
            asm volatile("cp.async.wait_group 0;" ::: "memory");
        }
        __syncthreads();
        const uint32_t st = sbase + (uint32_t)(it % 3) * 49152u;
#pragma unroll
        for (int ks = 0; ks < 4; ks++) {
            uint32_t afH[4][4], bfH[4][2], bfL[4][2];
#pragma unroll
            for (int mf = 0; mf < 4; mf++) {
                int row = mw + mf * 16 + (lane & 15);
                uint32_t bo = (uint32_t)(row << 7) + (uint32_t)(ks << 5) + ((lane >> 4) << 4);
                ldsm_x4(afH[mf], st + sw128(bo));
            }
#pragma unroll
            for (int half = 0; half < 2; half++) {
                int i2 = lane >> 3;
                int row = nw + half * 16 + ((i2 >> 1) << 3) + (lane & 7);
                uint32_t bo = (uint32_t)(row << 7) + (uint32_t)(ks << 5) + ((i2 & 1) << 4);
                uint32_t so = sw128(bo);
                uint32_t r[4];
                ldsm_x4(r, st + 16384 + so);
                bfH[half * 2][0] = r[0];     bfH[half * 2][1] = r[1];
                bfH[half * 2 + 1][0] = r[2]; bfH[half * 2 + 1][1] = r[3];
                if (twopass) {
                    ldsm_x4(r, st + 32768 + so);
                    bfL[half * 2][0] = r[0];     bfL[half * 2][1] = r[1];
                    bfL[half * 2 + 1][0] = r[2]; bfL[half * 2 + 1][1] = r[3];
                }
            }
            if (twopass) {
#pragma unroll
                for (int mf = 0; mf < 4; mf++)
#pragma unroll
                    for (int nf = 0; nf < 4; nf++) {
                        mma16816h(acc[mf][nf], afH[mf], bfH[nf]);
                        mma16816h(acc[mf][nf], afH[mf], bfL[nf]);
                    }
            } else {
#pragma unroll
                for (int mf = 0; mf < 4; mf++)
#pragma unroll
                    for (int nf = 0; nf < 4; nf++)
                        mma16816h(acc[mf][nf], afH[mf], bfH[nf]);
            }
        }
        if (it + 2 < TOT) issue(it + 2);
    }

    const int rb = m0 + mw + (lane >> 2);
    const int cb = n0 + nw + ((lane & 3) << 1);
    const int region = (n0 < ns1) ? 0 : ((n0 < ns2) ? 1 : 2);
    const int w0 = ns1, w1 = ns2 - ns1, w2 = N - ns2;
#pragma unroll
    for (int mf = 0; mf < 4; mf++) {
#pragma unroll
        for (int half = 0; half < 2; half++) {
            int row = rb + mf * 16 + half * 8;
#pragma unroll
            for (int nf = 0; nf < 4; nf++) {
                int col = cb + nf * 8;
                float vx = acc[mf][nf][half * 2 + 0];
                float vy = acc[mf][nf][half * 2 + 1];
                if (region == 0) {
                    float2 v; v.x = vx; v.y = vy;
                    *(float2*)(C0 + (size_t)row * w0 + col) = v;
                } else if (region == 1) {
                    int cc = col - ns1;
                    __nv_bfloat16 h0 = __float2bfloat16(vx);
                    __nv_bfloat16 h1 = __float2bfloat16(vy);
                    __nv_bfloat16 l0 = __float2bfloat16(vx - __bfloat162float(h0));
                    __nv_bfloat16 l1 = __float2bfloat16(vy - __bfloat162float(h1));
                    *(__nv_bfloat162*)(SHo + (size_t)row * w1 + cc) = __nv_bfloat162(h0, h1);
                    *(__nv_bfloat162*)(SLo + (size_t)row * w1 + cc) = __nv_bfloat162(l0, l1);
                } else {
                    int cc = col - ns2;
                    vx += bias[cc]; vy += bias[cc + 1];
                    float2 v; v.x = vx; v.y = vy;
                    *(float2*)(C2 + (size_t)row * w2 + cc) = v;
                }
            }
        }
    }
}

// ======================================================================
// akernel (verified): A = qd @ kexp^T, tril, split to bf16.
// ======================================================================
__global__ __launch_bounds__(256, 1)
void akernel(const __nv_bfloat16* __restrict__ QH, const __nv_bfloat16* __restrict__ QL,
             const __nv_bfloat16* __restrict__ KH, const __nv_bfloat16* __restrict__ KL,
             __nv_bfloat16* __restrict__ AH, __nv_bfloat16* __restrict__ AL)
{
    extern __shared__ char smemc[];
    const uint32_t sb = smem_u32(smemc);
    const uint32_t oQH = 0, oQL = 32768, oKH = 65536, oKL = 98304;
    const int tid = threadIdx.x;
    const int wid = tid >> 5, lane = tid & 31;
    const int h = blockIdx.x, ch = blockIdx.y, bb = blockIdx.z;
    const int m0 = bb * TT + ch * CHUNK;
    const int colQ = h * 128;
    const size_t chA = (size_t)((bb * NCH + ch) * HH + h) * 16384;

#pragma unroll
    for (int l = 0; l < 8; l++) {
        int idx = tid + (l << 8);
        int row = idx >> 4, u = idx & 15;
        int kb = u >> 3, sub = u & 7;
        uint32_t dst = (uint32_t)kb * 16384u + sw128((uint32_t)(row << 7) + (sub << 4));
        size_t so = (size_t)(m0 + row) * DHALF + colQ + kb * 64 + sub * 8;
        cpasync16(sb + oQH + dst, QH + so);
        cpasync16(sb + oQL + dst, QL + so);
        cpasync16(sb + oKH + dst, KH + so);
        cpasync16(sb + oKL + dst, KL + so);
    }
    asm volatile("cp.async.commit_group;" ::: "memory");
    asm volatile("cp.async.wait_group 0;" ::: "memory");
    __syncthreads();

    const int mw = (wid & 1) * 64, nw = (wid >> 1) * 32;
    float acc[4][4][4];
#pragma unroll
    for (int i = 0; i < 4; i++)
#pragma unroll
        for (int j = 0; j < 4; j++)
#pragma unroll
            for (int l = 0; l < 4; l++) acc[i][j][l] = 0.f;

    mma_combo<4>(acc, sb + oQH, 16384, sb + oKH, 16384, mw, nw, lane);
    mma_combo<4>(acc, sb + oQH, 16384, sb + oKL, 16384, mw, nw, lane);
    mma_combo<4>(acc, sb + oQL, 16384, sb + oKH, 16384, mw, nw, lane);

#pragma unroll
    for (int mf = 0; mf < 4; mf++) {
#pragma unroll
        for (int half = 0; half < 2; half++) {
            int i = mw + mf * 16 + half * 8 + (lane >> 2);
#pragma unroll
            for (int nf = 0; nf < 4; nf++) {
                int j = nw + nf * 8 + ((lane & 3) << 1);
                float v0 = (j     <= i) ? acc[mf][nf][half * 2 + 0] : 0.f;
                float v1 = (j + 1 <= i) ? acc[mf][nf][half * 2 + 1] : 0.f;
                __nv_bfloat16 h0 = __float2bfloat16(v0);
                __nv_bfloat16 h1 = __float2bfloat16(v1);
                __nv_bfloat16 l0 = __float2bfloat16(v0 - __bfloat162float(h0));
                __nv_bfloat16 l1 = __float2bfloat16(v1 - __bfloat162float(h1));
                size_t oi = chA + (size_t)i * 128 + j;
                *(__nv_bfloat162*)(AH + oi) = __nv_bfloat162(h0, h1);
                *(__nv_bfloat162*)(AL + oi) = __nv_bfloat162(l0, l1);
            }
        }
    }
}

// ======================================================================
// phase1 (verified R13): 96KB smem. o = tril(A)@v -> O, then kdT reuses
// the A region and U = kd^T@v -> U blob.
// ======================================================================
__global__ __launch_bounds__(256, 1)
void phase1_kernel(const __nv_bfloat16* __restrict__ AH, const __nv_bfloat16* __restrict__ AL,
                   const __nv_bfloat16* __restrict__ KDH, const __nv_bfloat16* __restrict__ KDL,
                   const __nv_bfloat16* __restrict__ VH, const __nv_bfloat16* __restrict__ VL,
                   float* __restrict__ O, float* __restrict__ U)
{
    extern __shared__ char smemc[];
    const uint32_t sb = smem_u32(smemc);
    const uint32_t oA = 0, oAl = 32768, oVH = 65536, oVL = 81920;  // 96K

    const int tid = threadIdx.x;
    const int wid = tid >> 5, lane = tid & 31;
    const int ch = blockIdx.x >> 2, vsl = blockIdx.x & 3;
    const int h = blockIdx.y, bb = blockIdx.z;
    const int m0 = bb * TT + ch * CHUNK;
    const int colQ = h * 128;
    const int colV = h * 256 + vsl * 64;
    const size_t chA = (size_t)((bb * NCH + ch) * HH + h) * 16384;
    const size_t ublob = (size_t)(((bb * HH + h) * 4 + vsl) * NCH + ch) * 8192;
    const int mw = (wid & 3) * 32, nw = (wid >> 2) * 32;

#pragma unroll
    for (int l = 0; l < 8; l++) {
        int idx = tid + (l << 8);
        int row = idx >> 4, u = idx & 15;
        int kb = u >> 3, sub = u & 7;
        uint32_t dst = (uint32_t)kb * 16384u + sw128((uint32_t)(row << 7) + (sub << 4));
        size_t sa = chA + (size_t)row * 128 + kb * 64 + sub * 8;
        cpasync16(sb + oA  + dst, AH + sa);
        cpasync16(sb + oAl + dst, AL + sa);
    }
    asm volatile("cp.async.commit_group;" ::: "memory");

#pragma unroll
    for (int l = 0; l < 16; l++) {
        int idx = tid + (l << 8);
        int j = idx >> 5, n = (idx & 31) << 1;
        uint32_t wv = *(const uint32_t*)(VH + (size_t)(m0 + j) * DD + colV + n);
        uint32_t wl = *(const uint32_t*)(VL + (size_t)(m0 + j) * DD + colV + n);
        uint32_t kbo = (uint32_t)(j >> 6) * 8192u;
        uint32_t off0 = kbo + sw128((uint32_t)(n << 7) + ((j & 63) << 1));
        uint32_t off1 = kbo + sw128((uint32_t)((n + 1) << 7) + ((j & 63) << 1));
        *(unsigned short*)(smemc + oVH + off0) = (unsigned short)(wv & 0xffff);
        *(unsigned short*)(smemc + oVH + off1) = (unsigned short)(wv >> 16);
        *(unsigned short*)(smemc + oVL + off0) = (unsigned short)(wl & 0xffff);
        *(unsigned short*)(smemc + oVL + off1) = (unsigned short)(wl >> 16);
    }
    asm volatile("cp.async.wait_group 0;" ::: "memory");
    __syncthreads();

    float acc[2][4][4];
#pragma unroll
    for (int i = 0; i < 2; i++)
#pragma unroll
        for (int j = 0; j < 4; j++)
#pragma unroll
            for (int l = 0; l < 4; l++) acc[i][j][l] = 0.f;
    mma_combo<2>(acc, sb + oA,  16384, sb + oVH, 8192, mw, nw, lane);
    mma_combo<2>(acc, sb + oA,  16384, sb + oVL, 8192, mw, nw, lane);
    mma_combo<2>(acc, sb + oAl, 16384, sb + oVH, 8192, mw, nw, lane);
#pragma unroll
    for (int mf = 0; mf < 2; mf++) {
#pragma unroll
        for (int half = 0; half < 2; half++) {
            int row = m0 + mw + mf * 16 + half * 8 + (lane >> 2);
#pragma unroll
            for (int nf = 0; nf < 4; nf++) {
                int col = colV + nw + nf * 8 + ((lane & 3) << 1);
                float2 v;
                v.x = acc[mf][nf][half * 2 + 0];
                v.y = acc[mf][nf][half * 2 + 1];
                *(float2*)&O[(size_t)row * DD + col] = v;
            }
        }
    }
    __syncthreads();

#pragma unroll
    for (int l = 0; l < 32; l++) {
        int idx = tid + (l << 8);
        int j = idx >> 6, d = (idx & 63) << 1;
        uint32_t wv = *(const uint32_t*)(KDH + (size_t)(m0 + j) * DHALF + colQ + d);
        uint32_t wl = *(const uint32_t*)(KDL + (size_t)(m0 + j) * DHALF + colQ + d);
        uint32_t kbo = (uint32_t)(j >> 6) * 16384u;
        uint32_t off0 = kbo + sw128((uint32_t)(d << 7) + ((j & 63) << 1));
        uint32_t off1 = kbo + sw128((uint32_t)((d + 1) << 7) + ((j & 63) << 1));
        *(unsigned short*)(smemc + oA  + off0) = (unsigned short)(wv & 0xffff);
        *(unsigned short*)(smemc + oA  + off1) = (unsigned short)(wv >> 16);
        *(unsigned short*)(smemc + oAl + off0) = (unsigned short)(wl & 0xffff);
        *(unsigned short*)(smemc + oAl + off1) = (unsigned short)(wl >> 16);
    }
    __syncthreads();

    float uacc[2][4][4];
#pragma unroll
    for (int i = 0; i < 2; i++)
#pragma unroll
        for (int j = 0; j < 4; j++)
#pragma unroll
            for (int l = 0; l < 4; l++) uacc[i][j][l] = 0.f;
    mma_combo<2>(uacc, sb + oA,  16384, sb + oVH, 8192, mw, nw, lane);
    mma_combo<2>(uacc, sb + oA,  16384, sb + oVL, 8192, mw, nw, lane);
    mma_combo<2>(uacc, sb + oAl, 16384, sb + oVH, 8192, mw, nw, lane);
#pragma unroll
    for (int mf = 0; mf < 2; mf++) {
#pragma unroll
        for (int half = 0; half < 2; half++) {
            int d = mw + mf * 16 + half * 8 + (lane >> 2);
            uint32_t kb = (uint32_t)(d >> 6) * 4096u;
            uint32_t d2b = (uint32_t)((d & 63) << 1);
#pragma unroll
            for (int nf = 0; nf < 4; nf++) {
                int n = nw + nf * 8 + ((lane & 3) << 1);
                uint32_t i0 = kb + (sw128(((uint32_t)n << 7) + d2b) >> 1);
                uint32_t i1 = kb + (sw128(((uint32_t)(n + 1) << 7) + d2b) >> 1);
                U[ublob + i0] = uacc[mf][nf][half * 2 + 0];
                U[ublob + i1] = uacc[mf][nf][half * 2 + 1];
            }
        }
    }
}

// ======================================================================
// scan (verified R11)
// ======================================================================
__global__ __launch_bounds__(256, 1)
void scan_kernel(const float* __restrict__ U, const float* __restrict__ DEC,
                 __nv_bfloat16* __restrict__ SBH, __nv_bfloat16* __restrict__ SBL)
{
    __shared__ float sdec[128];
    const int t = threadIdx.x;
    const int vsl = blockIdx.x, h = blockIdx.y, bb = blockIdx.z;
    const int blobbase = ((bb * HH + h) * 4 + vsl) * NCH;
    const int colQ = h * 128;

    int dbase[8];
#pragma unroll
    for (int g = 0; g < 8; g++) {
        uint32_t ibase = (uint32_t)(t + g * 256) * 4;
        uint32_t braw = sw128((ibase & 4095) * 2);
        dbase[g] = (int)(ibase >> 12) * 64 + (int)((braw & 127) >> 1);
    }

    float S[32];
#pragma unroll
    for (int i = 0; i < 32; i++) S[i] = 0.f;

    for (int ch = 0; ch < NCH; ch++) {
        if (t < 128) sdec[t] = DEC[(size_t)(bb * NCH + ch) * DHALF + colQ + t];
        const size_t blob = (size_t)(blobbase + ch) * 8192;
#pragma unroll
        for (int g = 0; g < 8; g++) {
            uint32_t ibase = (uint32_t)(t + g * 256) * 4;
            float v0 = S[g * 4 + 0], v1 = S[g * 4 + 1], v2 = S[g * 4 + 2], v3 = S[g * 4 + 3];
            __nv_bfloat16 h0 = __float2bfloat16(v0), h1 = __float2bfloat16(v1);
            __nv_bfloat16 h2 = __float2bfloat16(v2), h3 = __float2bfloat16(v3);
            *(__nv_bfloat162*)(SBH + blob + ibase)     = __nv_bfloat162(h0, h1);
            *(__nv_bfloat162*)(SBH + blob + ibase + 2) = __nv_bfloat162(h2, h3);
            __nv_bfloat16 l0 = __float2bfloat16(v0 - __bfloat162float(h0));
            __nv_bfloat16 l1 = __float2bfloat16(v1 - __bfloat162float(h1));
            __nv_bfloat16 l2 = __float2bfloat16(v2 - __bfloat162float(h2));
            __nv_bfloat16 l3 = __float2bfloat16(v3 - __bfloat162float(h3));
            *(__nv_bfloat162*)(SBL + blob + ibase)     = __nv_bfloat162(l0, l1);
            *(__nv_bfloat162*)(SBL + blob + ibase + 2) = __nv_bfloat162(l2, l3);
        }
        __syncthreads();
#pragma unroll
        for (int g = 0; g < 8; g++) {
            uint32_t ibase = (uint32_t)(t + g * 256) * 4;
            float4 u = *(const float4*)(U + blob + ibase);
            int d0 = dbase[g];
            S[g * 4 + 0] = sdec[d0 + 0] * S[g * 4 + 0] + u.x;
            S[g * 4 + 1] = sdec[d0 + 1] * S[g * 4 + 1] + u.y;
            S[g * 4 + 2] = sdec[d0 + 2] * S[g * 4 + 2] + u.z;
            S[g * 4 + 3] = sdec[d0 + 3] * S[g * 4 + 3] + u.w;
        }
        __syncthreads();
    }
}

// ======================================================================
// o2 (verified R11): O += qd @ S_ch
// ======================================================================
__global__ __launch_bounds__(256, 1)
void o2_kernel(const __nv_bfloat16* __restrict__ QH, const __nv_bfloat16* __restrict__ QL,
               const __nv_bfloat16* __restrict__ SBH, const __nv_bfloat16* __restrict__ SBL,
               float* __restrict__ O)
{
    extern __shared__ char smemc[];
    const uint32_t sb = smem_u32(smemc);
    const uint32_t oQH = 0, oQL = 32768, oSH = 65536, oSL = 81920;

    const int tid = threadIdx.x;
    const int wid = tid >> 5, lane = tid & 31;
    const int ch = blockIdx.x >> 2, vsl = blockIdx.x & 3;
    const int h = blockIdx.y, bb = blockIdx.z;
    const int m0 = bb * TT + ch * CHUNK;
    const int colQ = h * 128;
    const int colV = h * 256 + vsl * 64;
    const size_t blob = (size_t)(((bb * HH + h) * 4 + vsl) * NCH + ch) * 8192;
    const int mw = (wid & 3) * 32, nw = (wid >> 2) * 32;

#pragma unroll
    for (int l = 0; l < 8; l++) {
        int idx = tid + (l << 8);
        int row = idx >> 4, u = idx & 15;
        int kb = u >> 3, sub = u & 7;
        uint32_t dst = (uint32_t)kb * 16384u + sw128((uint32_t)(row << 7) + (sub << 4));
        size_t so = (size_t)(m0 + row) * DHALF + colQ + kb * 64 + sub * 8;
        cpasync16(sb + oQH + dst, QH + so);
        cpasync16(sb + oQL + dst, QL + so);
    }
#pragma unroll
    for (int l = 0; l < 4; l++) {
        int i = tid + (l << 8);
        cpasync16(sb + oSH + (i << 4), SBH + blob + (size_t)i * 8);
        cpasync16(sb + oSL + (i << 4), SBL + blob + (size_t)i * 8);
    }
    asm volatile("cp.async.commit_group;" ::: "memory");
    asm volatile("cp.async.wait_group 0;" ::: "memory");
    __syncthreads();

    float acc[2][4][4];
#pragma unroll
    for (int i = 0; i < 2; i++)
#pragma unroll
        for (int j = 0; j < 4; j++)
#pragma unroll
            for (int l = 0; l < 4; l++) acc[i][j][l] = 0.f;

    mma_combo<2>(acc, sb + oQH, 16384, sb + oSH, 8192, mw, nw, lane);
    mma_combo<2>(acc, sb + oQH, 16384, sb + oSL, 8192, mw, nw, lane);
    mma_combo<2>(acc, sb + oQL, 16384, sb + oSH, 8192, mw, nw, lane);

#pragma unroll
    for (int mf = 0; mf < 2; mf++) {
#pragma unroll
        for (int half = 0; half < 2; half++) {
            int row = m0 + mw + mf * 16 + half * 8 + (lane >> 2);
#pragma unroll
            for (int nf = 0; nf < 4; nf++) {
                int col = colV + nw + nf * 8 + ((lane & 3) << 1);
                float2 v = *(float2*)&O[(size_t)row * DD + col];
                v.x += acc[mf][nf][half * 2 + 0];
                v.y += acc[mf][nf][half * 2 + 1];
                *(float2*)&O[(size_t)row * DD + col] = v;
            }
        }
    }
}

// ======================================================================
// x -> fp16
// ======================================================================
__global__ void xhalf(const float4* __restrict__ X, __half* __restrict__ H, int n4)
{
    int i = blockIdx.x * blockDim.x + threadIdx.x;
    if (i >= n4) return;
    float4 v = X[i];
    __half2* Hp = (__half2*)H;
    Hp[i * 2]     = __floats2half2_rn(v.x, v.y);
    Hp[i * 2 + 1] = __floats2half2_rn(v.z, v.w);
}

// ======================================================================
// transpose W -> combined WT fp16 hi/lo
// ======================================================================
__global__ void wsplit_t(const float* __restrict__ W, __half* __restrict__ Th,
                         __half* __restrict__ Tl, int K, int N, int rowoff, float alpha)
{
    __shared__ float t[32][33];
    const int n0 = blockIdx.x * 32, k0 = blockIdx.y * 32;
    const int tx = threadIdx.x, ty = threadIdx.y;
#pragma unroll
    for (int i = 0; i < 4; i++) {
        int k = ty + i * 8;
        t[k][tx] = W[(size_t)(k0 + k) * N + n0 + tx];
    }
    __syncthreads();
#pragma unroll
    for (int i = 0; i < 4; i++) {
        int n = ty + i * 8;
        float v = t[tx][n] * alpha;
        __half h = __float2half(v);
        size_t oi = (size_t)(rowoff + n0 + n) * K + k0 + tx;
        Th[oi] = h;
        Tl[oi] = __float2half(v - __half2float(h));
    }
}

// ======================================================================
// kg1
// ======================================================================
__global__ void kg1_kernel(const float* __restrict__ x, const float* __restrict__ W1,
                           float* __restrict__ out)
{
    const int wid = threadIdx.x >> 5, lane = threadIdx.x & 31;
    const int row = blockIdx.x * 8 + wid;
    const float* xp = x + (size_t)row * DD;
    float acc[16];
#pragma unroll
    for (int c = 0; c < 16; c++) acc[c] = 0.f;
    for (int k = lane; k < DD; k += 32) {
        float xv = xp[k];
        const float4* wp = (const float4*)(W1 + (size_t)k * 16);
        float4 w0 = wp[0], w1 = wp[1], w2 = wp[2], w3 = wp[3];
        acc[0]  += xv * w0.x; acc[1]  += xv * w0.y; acc[2]  += xv * w0.z; acc[3]  += xv * w0.w;
        acc[4]  += xv * w1.x; acc[5]  += xv * w1.y; acc[6]  += xv * w1.z; acc[7]  += xv * w1.w;
        acc[8]  += xv * w2.x; acc[9]  += xv * w2.y; acc[10] += xv * w2.z; acc[11] += xv * w2.w;
        acc[12] += xv * w3.x; acc[13] += xv * w3.y; acc[14] += xv * w3.z; acc[15] += xv * w3.w;
    }
#pragma unroll
    for (int c = 0; c < 16; c++) {
        float v = acc[c];
#pragma unroll
        for (int off = 16; off; off >>= 1) v += __shfl_xor_sync(0xFFFFFFFFu, v, off);
        if (lane == 0) out[(size_t)row * 16 + c] = v;
    }
}

// ======================================================================
// gk
// ======================================================================
__global__ void gk_kernel(const float* __restrict__ KG1,
                          const float* __restrict__ W2,
                          const float* __restrict__ b2,
                          float* __restrict__ GK)
{
    __shared__ float a[16];
    int m = blockIdx.x;
    if (threadIdx.x < 16) a[threadIdx.x] = KG1[(size_t)m * 16 + threadIdx.x];
    __syncthreads();
    for (int c = threadIdx.x; c < DHALF; c += 128) {
        float z = b2[c];
#pragma unroll
        for (int r = 0; r < 16; r++) z = fmaf(a[r], W2[(size_t)r * DHALF + c], z);
        float e = __expf(-fabsf(z));
        float l = __logf(1.f + e);
        float ls = (z >= 0.f) ? -l : (z - l);
        GK[(size_t)m * DHALF + c] = ls * INV_NORM_GK;
    }
}

// ======================================================================
// prep
// ======================================================================
__global__ void prep_kernel(const float* __restrict__ QK,
                            const float* __restrict__ GK,
                            __nv_bfloat16* __restrict__ QHo, __nv_bfloat16* __restrict__ QLo,
                            __nv_bfloat16* __restrict__ KHo, __nv_bfloat16* __restrict__ KLo,
                            __nv_bfloat16* __restrict__ KDHo, __nv_bfloat16* __restrict__ KDLo,
                            float* __restrict__ DEC)
{
    int g = blockIdx.x * blockDim.x + threadIdx.x;
    int col = g & (DHALF - 1);
    int bc  = g >> 10;
    int row0 = ((bc >> 4) * TT) + ((bc & 15) * CHUNK);
    size_t baseg = (size_t)row0 * DHALF + col;
    size_t baseq = (size_t)row0 * 2048 + col;

    float gs = 0.f;
#pragma unroll 4
    for (int i = 0; i < CHUNK; i++) gs += GK[baseg + (size_t)i * DHALF];
    float egs = __expf(gs);

    float gc = 0.f;
    for (int i = 0; i < CHUNK; i++) {
        size_t idx = baseg + (size_t)i * DHALF;
        size_t qdx = baseq + (size_t)i * 2048;
        gc += GK[idx];
        float eg = __expf(gc);
        float qd = QK[qdx] * eg;
        float kv = QK[qdx + 1024];
        float ke = __fdividef(kv, eg);
        float kd = ke * egs;
        __nv_bfloat16 qh = __float2bfloat16(qd);
        __nv_bfloat16 kh = __float2bfloat16(ke);
        __nv_bfloat16 dh = __float2bfloat16(kd);
        QHo[idx]  = qh; QLo[idx]  = __float2bfloat16(qd - __bfloat162float(qh));
        KHo[idx]  = kh; KLo[idx]  = __float2bfloat16(ke - __bfloat162float(kh));
        KDHo[idx] = dh; KDLo[idx] = __float2bfloat16(kd - __bfloat162float(dh));
    }
    DEC[(size_t)bc * DHALF + col] = egs;
}

// ======================================================================
// norm * silu -> fp16
// ======================================================================
__global__ void norm_gate_kernel(const float* __restrict__ O,
                                 const float* __restrict__ G,
                                 __half* __restrict__ PH)
{
    int m = blockIdx.x, h = blockIdx.y;
    int tid = threadIdx.x;
    size_t idx = (size_t)m * DD + h * DV + tid;
    float v = O[idx];
    float s = v, s2 = v * v;
#pragma unroll
    for (int off = 16; off; off >>= 1) {
        s  += __shfl_xor_sync(0xFFFFFFFFu, s,  off);
        s2 += __shfl_xor_sync(0xFFFFFFFFu, s2, off);
    }
    __shared__ float ws[8], ws2[8];
    int w = tid >> 5, l = tid & 31;
    if (l == 0) { ws[w] = s; ws2[w] = s2; }
    __syncthreads();
    float ts = 0.f, ts2 = 0.f;
#pragma unroll
    for (int i = 0; i < 8; i++) { ts += ws[i]; ts2 += ws2[i]; }
    float mu = ts * (1.f / 256.f);
    float var = ts2 * (1.f / 256.f) - mu * mu;
    float nv = (v - mu) * rsqrtf(var + 1e-5f);
    float gt = G[idx];
    float sg = gt / (1.f + __expf(-gt));
    PH[idx] = __float2half(sg * nv);
}

// ======================================================================
extern "C" void kernel_launch(void* const* d_in, const int* in_sizes, int n_in,
                              void* d_out, int out_size)
{
    const float* x    = (const float*)d_in[0];
    const float* Wq   = (const float*)d_in[1];
    const float* Wk   = (const float*)d_in[2];
    const float* Wkg1 = (const float*)d_in[3];
    const float* Wkg2 = (const float*)d_in[4];
    const float* bkg2 = (const float*)d_in[5];
    const float* Wv   = (const float*)d_in[6];
    const float* Wg   = (const float*)d_in[7];
    const float* bg   = (const float*)d_in[8];
    const float* Wo   = (const float*)d_in[9];
    float* out = (float*)d_out;

    float *pQK, *pGK, *pKG1, *pDEC, *pG, *pO, *pU;
    __half *pXH, *pWTH, *pWTL, *pPH;
    __nv_bfloat16 *pQH, *pQL, *pKH, *pKL, *pKDH, *pKDL, *pVH, *pVL, *pAH, *pAL, *pSBH, *pSBL;
    cudaGetSymbolAddress((void**)&pQK,  g_QK);
    cudaGetSymbolAddress((void**)&pGK,  g_GK);
    cudaGetSymbolAddress((void**)&pKG1, g_KG1);
    cudaGetSymbolAddress((void**)&pDEC, g_DEC);
    cudaGetSymbolAddress((void**)&pG,   g_G);
    cudaGetSymbolAddress((void**)&pO,   g_O);
    cudaGetSymbolAddress((void**)&pU,   g_U);
    cudaGetSymbolAddress((void**)&pXH,  g_XH);
    cudaGetSymbolAddress((void**)&pWTH, g_WTH);
    cudaGetSymbolAddress((void**)&pWTL, g_WTL);
    cudaGetSymbolAddress((void**)&pPH,  g_PH);
    cudaGetSymbolAddress((void**)&pQH,  g_QH);
    cudaGetSymbolAddress((void**)&pQL,  g_QL);
    cudaGetSymbolAddress((void**)&pKH,  g_KH);
    cudaGetSymbolAddress((void**)&pKL,  g_KL);
    cudaGetSymbolAddress((void**)&pKDH, g_KDH);
    cudaGetSymbolAddress((void**)&pKDL, g_KDL);
    cudaGetSymbolAddress((void**)&pVH,  g_VH);
    cudaGetSymbolAddress((void**)&pVL,  g_VL);
    cudaGetSymbolAddress((void**)&pAH,  g_AH);
    cudaGetSymbolAddress((void**)&pAL,  g_AL);
    cudaGetSymbolAddress((void**)&pSBH, g_SBH);
    cudaGetSymbolAddress((void**)&pSBL, g_SBL);

    cudaFuncSetAttribute(gemm2h,        cudaFuncAttributeMaxDynamicSharedMemorySize, 147456);
    cudaFuncSetAttribute(akernel,       cudaFuncAttributeMaxDynamicSharedMemorySize, 131072);
    cudaFuncSetAttribute(phase1_kernel, cudaFuncAttributeMaxDynamicSharedMemorySize, 98304);
    cudaFuncSetAttribute(o2_kernel,     cudaFuncAttributeMaxDynamicSharedMemorySize, 98304);

    dim3 tb(32, 8);
    int n4 = MROWS * DD / 4;

    // x -> fp16 ; weights -> combined WT fp16 hi/lo (Q|K*scale|V|G|O)
    xhalf<<<(n4 + 255) / 256, 256>>>((const float4*)x, pXH, n4);
    kg1_kernel<<<MROWS / 8, 256>>>(x, Wkg1, pKG1);
    wsplit_t<<<dim3(DHALF / 32, DD / 32), tb>>>(Wq, pWTH, pWTL, DD, DHALF, 0, 1.0f);
    wsplit_t<<<dim3(DHALF / 32, DD / 32), tb>>>(Wk, pWTH, pWTL, DD, DHALF, 1024, SCALING);
    wsplit_t<<<dim3(DD / 32, DD / 32), tb>>>(Wv, pWTH, pWTL, DD, DD, 2048, 1.0f);
    wsplit_t<<<dim3(DD / 32, DD / 32), tb>>>(Wg, pWTH, pWTL, DD, DD, 4096, 1.0f);
    wsplit_t<<<dim3(DD / 32, DD / 32), tb>>>(Wo, pWTH, pWTL, DD, DD, 6144, 1.0f);

    // fused Q+K+V+G projection (N=6144): QK 2-pass fp32 | V 1-pass bf16-split | G 1-pass fp32+bias
    gemm2h<<<dim3(6144 / 128, MROWS / 128), 256, 147456>>>(pXH, pWTH, pWTL,
        pQK, pVH, pVL, pG, bg, MROWS, 6144, DD, 2048, 4096, 2048);

    // gk + decay precompute
    gk_kernel<<<MROWS, 128>>>(pKG1, Wkg2, bkg2, pGK);
    prep_kernel<<<256, 256>>>(pQK, pGK, pQH, pQL, pKH, pKL, pKDH, pKDL, pDEC);

    // A chunks
    akernel<<<dim3(HH, NCH, BB), 256, 131072>>>(pQH, pQL, pKH, pKL, pAH, pAL);

    // parallel: O_intra + U chunks
    phase1_kernel<<<dim3(NCH * 4, HH, BB), 256, 98304>>>(pAH, pAL, pKDH, pKDL,
                                                         pVH, pVL, pO, pU);
    // fast elementwise scan -> S blobs
    scan_kernel<<<dim3(4, HH, BB), 256>>>(pU, pDEC, pSBH, pSBL);
    // parallel: O += qd @ S
    o2_kernel<<<dim3(NCH * 4, HH, BB), 256, 98304>>>(pQH, pQL, pSBH, pSBL, pO);

    // groupnorm + silu gate -> fp16
    norm_gate_kernel<<<dim3(MROWS, HH), 256>>>(pO, pG, pPH);

    // output projection (2-pass, fp32 out)
    gemm2h<<<dim3(2048 / 128, MROWS / 128), 256, 147456>>>(pPH,
        pWTH + (size_t)6144 * DD, pWTL + (size_t)6144 * DD,
        out, nullptr, nullptr, nullptr, nullptr, MROWS, 2048, DD, 2048, 2048, 2048);
}

// round 17
// speedup vs baseline: 1.5269x; 1.3083x over previous
#include <cuda_runtime.h>
#include <cuda_bf16.h>
#include <cuda_fp16.h>
#include <math.h>
#include <stdint.h>

// ---------------- problem constants ----------------
#define BB     4
#define TT     2048
#define DD     2048
#define HH     8
#define DK     128
#define DV     256
#define CHUNK  128
#define NCH    16
#define MROWS  (BB*TT)      // 8192
#define DHALF  (DD/2)       // 1024
#define SCALING 0.0625f
#define INV_NORM_GK (1.0f/16.0f)
#define NCHUNKS (BB*NCH*HH) // 512
#define NBLOBS  (BB*HH*4*NCH) // 2048
#define WTROWS 8192

// ---------------- scratch ----------------
__device__ float g_QK [(size_t)MROWS * 2048];
__device__ float g_GK [(size_t)MROWS * DHALF];
__device__ float g_KG1[(size_t)MROWS * 16];
__device__ float g_DEC[(size_t)BB * NCH * DHALF];
__device__ float g_G  [(size_t)MROWS * DD];
__device__ float g_O  [(size_t)MROWS * DD];
__device__ float g_U  [(size_t)NBLOBS * 8192];
__device__ __half g_XH [(size_t)MROWS * DD];
__device__ __half g_WTH[(size_t)WTROWS * DD];
__device__ __half g_PH [(size_t)MROWS * DD];
__device__ __nv_bfloat16 g_QH [(size_t)MROWS * DHALF];
__device__ __nv_bfloat16 g_QL [(size_t)MROWS * DHALF];
__device__ __nv_bfloat16 g_KH [(size_t)MROWS * DHALF];
__device__ __nv_bfloat16 g_KL [(size_t)MROWS * DHALF];
__device__ __nv_bfloat16 g_KDH[(size_t)MROWS * DHALF];
__device__ __nv_bfloat16 g_KDL[(size_t)MROWS * DHALF];
__device__ __nv_bfloat16 g_VH [(size_t)MROWS * DD];
__device__ __nv_bfloat16 g_VL [(size_t)MROWS * DD];
__device__ __nv_bfloat16 g_AH [(size_t)NCHUNKS * CHUNK * CHUNK];
__device__ __nv_bfloat16 g_AL [(size_t)NCHUNKS * CHUNK * CHUNK];
__device__ __nv_bfloat16 g_SBH[(size_t)NBLOBS * 64 * 128];
__device__ __nv_bfloat16 g_SBL[(size_t)NBLOBS * 64 * 128];

// ================= helpers =================
__device__ __forceinline__ uint32_t smem_u32(const void* p) {
    uint32_t a;
    asm("{ .reg .u64 t; cvta.to.shared.u64 t, %1; cvt.u32.u64 %0, t; }" : "=r"(a) : "l"(p));
    return a;
}
__device__ __forceinline__ void cpasync16(uint32_t dst, const void* src) {
    asm volatile("cp.async.cg.shared.global [%0], [%1], 16;" :: "r"(dst), "l"(src) : "memory");
}
__device__ __forceinline__ void ldsm_x4(uint32_t* r, uint32_t addr) {
    asm volatile("ldmatrix.sync.aligned.m8n8.x4.shared.b16 {%0,%1,%2,%3}, [%4];"
                 : "=r"(r[0]), "=r"(r[1]), "=r"(r[2]), "=r"(r[3]) : "r"(addr));
}
__device__ __forceinline__ void mma16816(float* c, const uint32_t* a, const uint32_t* b) {
    asm volatile(
        "mma.sync.aligned.m16n8k16.row.col.f32.bf16.bf16.f32 "
        "{%0,%1,%2,%3}, {%4,%5,%6,%7}, {%8,%9}, {%0,%1,%2,%3};"
        : "+f"(c[0]), "+f"(c[1]), "+f"(c[2]), "+f"(c[3])
        : "r"(a[0]), "r"(a[1]), "r"(a[2]), "r"(a[3]), "r"(b[0]), "r"(b[1]));
}
__device__ __forceinline__ void mma16816h(float* c, const uint32_t* a, const uint32_t* b) {
    asm volatile(
        "mma.sync.aligned.m16n8k16.row.col.f32.f16.f16.f32 "
        "{%0,%1,%2,%3}, {%4,%5,%6,%7}, {%8,%9}, {%0,%1,%2,%3};"
        : "+f"(c[0]), "+f"(c[1]), "+f"(c[2]), "+f"(c[3])
        : "r"(a[0]), "r"(a[1]), "r"(a[2]), "r"(a[3]), "r"(b[0]), "r"(b[1]));
}
static __device__ __forceinline__ uint32_t sw128(uint32_t o) { return o ^ ((o >> 3) & 0x70); }

// acc[MF][4][4] += A_tile @ B_tile^T over K=128 (2 sw128 K-subtiles) [bf16]
template<int MF>
__device__ __forceinline__ void mma_combo(float (*acc)[4][4], uint32_t Ab, uint32_t abs_,
                                          uint32_t Bb, uint32_t bbs, int mw, int nw, int lane)
{
#pragma unroll
    for (int kb = 0; kb < 2; kb++) {
#pragma unroll
        for (int ks = 0; ks < 4; ks++) {
            uint32_t af[MF][4];
#pragma unroll
            for (int mf = 0; mf < MF; mf++) {
                int row = mw + mf * 16 + (lane & 15);
                uint32_t bo = (uint32_t)(row << 7) + (uint32_t)(ks << 5) + ((lane >> 4) << 4);
                ldsm_x4(af[mf], Ab + kb * abs_ + sw128(bo));
            }
            uint32_t bfr[4][2];
#pragma unroll
            for (int half = 0; half < 2; half++) {
                int i2 = lane >> 3;
                int row = nw + half * 16 + ((i2 >> 1) << 3) + (lane & 7);
                uint32_t bo = (uint32_t)(row << 7) + (uint32_t)(ks << 5) + ((i2 & 1) << 4);
                uint32_t r[4];
                ldsm_x4(r, Bb + kb * bbs + sw128(bo));
                bfr[half * 2][0] = r[0];     bfr[half * 2][1] = r[1];
                bfr[half * 2 + 1][0] = r[2]; bfr[half * 2 + 1][1] = r[3];
            }
#pragma unroll
            for (int mf = 0; mf < MF; mf++)
#pragma unroll
                for (int nf = 0; nf < 4; nf++)
                    mma16816(acc[mf][nf], af[mf], bfr[nf]);
        }
    }
}

// ======================================================================
// gemm1h: single-pass fp16 GEMM (128x128, 3-stage, 256 thr, 2 CTA/SM).
// Per stage: A (16KB) + B (16KB) = 32KB; 3 stages = 96KB.
// 3-region epilogue (block-uniform; ns1/ns2 multiples of 128):
//   n0 <  ns1 : fp32 -> C0 (stride ns1)
//   n0 <  ns2 : bf16 split -> SHo/SLo (stride ns2-ns1)
//   else      : fp32 + bias -> C2 (stride N-ns2)
// ======================================================================
__global__ __launch_bounds__(256, 2)
void gemm1h(const __half* __restrict__ AHp, const __half* __restrict__ BHp,
            float* __restrict__ C0, __nv_bfloat16* __restrict__ SHo, __nv_bfloat16* __restrict__ SLo,
            float* __restrict__ C2, const float* __restrict__ bias,
            int M, int N, int K, int ns1, int ns2)
{
    extern __shared__ char smem[];
    const uint32_t sbase = smem_u32(smem);
    const int tid = threadIdx.x;
    const int wid = tid >> 5, lane = tid & 31;
    const int m0 = blockIdx.y * 128, n0 = blockIdx.x * 128;
    const int mw = (wid & 1) * 64, nw = (wid >> 1) * 32;
    const int TOT = K >> 6;

    float acc[4][4][4];
#pragma unroll
    for (int i = 0; i < 4; i++)
#pragma unroll
        for (int j = 0; j < 4; j++)
#pragma unroll
            for (int l = 0; l < 4; l++) acc[i][j][l] = 0.f;

    auto issue = [&](int it) {
        const int k0 = it << 6;
        const uint32_t st = sbase + (uint32_t)(it % 3) * 32768u;
#pragma unroll
        for (int l = 0; l < 4; l++) {
            int c = tid + (l << 8);
            int row = c >> 3;
            uint32_t dst = sw128((uint32_t)(row << 7) + ((c & 7) << 4));
            int el = (c & 7) << 3;
            cpasync16(st + dst,         AHp + (size_t)(m0 + row) * K + k0 + el);
            cpasync16(st + 16384 + dst, BHp + (size_t)(n0 + row) * K + k0 + el);
        }
        asm volatile("cp.async.commit_group;" ::: "memory");
    };

    issue(0);
    if (TOT > 1) issue(1);
    for (int it = 0; it < TOT; it++) {
        if (it + 1 < TOT) {
            asm volatile("cp.async.wait_group 1;" ::: "memory");
        } else {
            asm volatile("cp.async.wait_group 0;" ::: "memory");
        }
        __syncthreads();
        const uint32_t st = sbase + (uint32_t)(it % 3) * 32768u;
#pragma unroll
        for (int ks = 0; ks < 4; ks++) {
            uint32_t afH[4][4], bfH[4][2];
#pragma unroll
            for (int mf = 0; mf < 4; mf++) {
                int row = mw + mf * 16 + (lane & 15);
                uint32_t bo = (uint32_t)(row << 7) + (uint32_t)(ks << 5) + ((lane >> 4) << 4);
                ldsm_x4(afH[mf], st + sw128(bo));
            }
#pragma unroll
            for (int half = 0; half < 2; half++) {
                int i2 = lane >> 3;
                int row = nw + half * 16 + ((i2 >> 1) << 3) + (lane & 7);
                uint32_t bo = (uint32_t)(row << 7) + (uint32_t)(ks << 5) + ((i2 & 1) << 4);
                uint32_t r[4];
                ldsm_x4(r, st + 16384 + sw128(bo));
                bfH[half * 2][0] = r[0];     bfH[half * 2][1] = r[1];
                bfH[half * 2 + 1][0] = r[2]; bfH[half * 2 + 1][1] = r[3];
            }
#pragma unroll
            for (int mf = 0; mf < 4; mf++)
#pragma unroll
                for (int nf = 0; nf < 4; nf++)
                    mma16816h(acc[mf][nf], afH[mf], bfH[nf]);
        }
        if (it + 2 < TOT) issue(it + 2);
    }

    const int rb = m0 + mw + (lane >> 2);
    const int cb = n0 + nw + ((lane & 3) << 1);
    const int region = (n0 < ns1) ? 0 : ((n0 < ns2) ? 1 : 2);
    const int w0 = ns1, w1 = ns2 - ns1, w2 = N - ns2;
#pragma unroll
    for (int mf = 0; mf < 4; mf++) {
#pragma unroll
        for (int half = 0; half < 2; half++) {
            int row = rb + mf * 16 + half * 8;
#pragma unroll
            for (int nf = 0; nf < 4; nf++) {
                int col = cb + nf * 8;
                float vx = acc[mf][nf][half * 2 + 0];
                float vy = acc[mf][nf][half * 2 + 1];
                if (region == 0) {
                    float2 v; v.x = vx; v.y = vy;
                    *(float2*)(C0 + (size_t)row * w0 + col) = v;
                } else if (region == 1) {
                    int cc = col - ns1;
                    __nv_bfloat16 h0 = __float2bfloat16(vx);
                    __nv_bfloat16 h1 = __float2bfloat16(vy);
                    __nv_bfloat16 l0 = __float2bfloat16(vx - __bfloat162float(h0));
                    __nv_bfloat16 l1 = __float2bfloat16(vy - __bfloat162float(h1));
                    *(__nv_bfloat162*)(SHo + (size_t)row * w1 + cc) = __nv_bfloat162(h0, h1);
                    *(__nv_bfloat162*)(SLo + (size_t)row * w1 + cc) = __nv_bfloat162(l0, l1);
                } else {
                    int cc = col - ns2;
                    vx += bias[cc]; vy += bias[cc + 1];
                    float2 v; v.x = vx; v.y = vy;
                    *(float2*)(C2 + (size_t)row * w2 + cc) = v;
                }
            }
        }
    }
}

// ======================================================================
// akernel (verified): A = qd @ kexp^T, tril, split to bf16.
// ======================================================================
__global__ __launch_bounds__(256, 1)
void akernel(const __nv_bfloat16* __restrict__ QH, const __nv_bfloat16* __restrict__ QL,
             const __nv_bfloat16* __restrict__ KH, const __nv_bfloat16* __restrict__ KL,
             __nv_bfloat16* __restrict__ AH, __nv_bfloat16* __restrict__ AL)
{
    extern __shared__ char smemc[];
    const uint32_t sb = smem_u32(smemc);
    const uint32_t oQH = 0, oQL = 32768, oKH = 65536, oKL = 98304;
    const int tid = threadIdx.x;
    const int wid = tid >> 5, lane = tid & 31;
    const int h = blockIdx.x, ch = blockIdx.y, bb = blockIdx.z;
    const int m0 = bb * TT + ch * CHUNK;
    const int colQ = h * 128;
    const size_t chA = (size_t)((bb * NCH + ch) * HH + h) * 16384;

#pragma unroll
    for (int l = 0; l < 8; l++) {
        int idx = tid + (l << 8);
        int row = idx >> 4, u = idx & 15;
        int kb = u >> 3, sub = u & 7;
        uint32_t dst = (uint32_t)kb * 16384u + sw128((uint32_t)(row << 7) + (sub << 4));
        size_t so = (size_t)(m0 + row) * DHALF + colQ + kb * 64 + sub * 8;
        cpasync16(sb + oQH + dst, QH + so);
        cpasync16(sb + oQL + dst, QL + so);
        cpasync16(sb + oKH + dst, KH + so);
        cpasync16(sb + oKL + dst, KL + so);
    }
    asm volatile("cp.async.commit_group;" ::: "memory");
    asm volatile("cp.async.wait_group 0;" ::: "memory");
    __syncthreads();

    const int mw = (wid & 1) * 64, nw = (wid >> 1) * 32;
    float acc[4][4][4];
#pragma unroll
    for (int i = 0; i < 4; i++)
#pragma unroll
        for (int j = 0; j < 4; j++)
#pragma unroll
            for (int l = 0; l < 4; l++) acc[i][j][l] = 0.f;

    mma_combo<4>(acc, sb + oQH, 16384, sb + oKH, 16384, mw, nw, lane);
    mma_combo<4>(acc, sb + oQH, 16384, sb + oKL, 16384, mw, nw, lane);
    mma_combo<4>(acc, sb + oQL, 16384, sb + oKH, 16384, mw, nw, lane);

#pragma unroll
    for (int mf = 0; mf < 4; mf++) {
#pragma unroll
        for (int half = 0; half < 2; half++) {
            int i = mw + mf * 16 + half * 8 + (lane >> 2);
#pragma unroll
            for (int nf = 0; nf < 4; nf++) {
                int j = nw + nf * 8 + ((lane & 3) << 1);
                float v0 = (j     <= i) ? acc[mf][nf][half * 2 + 0] : 0.f;
                float v1 = (j + 1 <= i) ? acc[mf][nf][half * 2 + 1] : 0.f;
                __nv_bfloat16 h0 = __float2bfloat16(v0);
                __nv_bfloat16 h1 = __float2bfloat16(v1);
                __nv_bfloat16 l0 = __float2bfloat16(v0 - __bfloat162float(h0));
                __nv_bfloat16 l1 = __float2bfloat16(v1 - __bfloat162float(h1));
                size_t oi = chA + (size_t)i * 128 + j;
                *(__nv_bfloat162*)(AH + oi) = __nv_bfloat162(h0, h1);
                *(__nv_bfloat162*)(AL + oi) = __nv_bfloat162(l0, l1);
            }
        }
    }
}

// ======================================================================
// phase1 (verified R13): 96KB smem. o = tril(A)@v -> O, then kdT reuses
// the A region and U = kd^T@v -> U blob.
// ======================================================================
__global__ __launch_bounds__(256, 1)
void phase1_kernel(const __nv_bfloat16* __restrict__ AH, const __nv_bfloat16* __restrict__ AL,
                   const __nv_bfloat16* __restrict__ KDH, const __nv_bfloat16* __restrict__ KDL,
                   const __nv_bfloat16* __restrict__ VH, const __nv_bfloat16* __restrict__ VL,
                   float* __restrict__ O, float* __restrict__ U)
{
    extern __shared__ char smemc[];
    const uint32_t sb = smem_u32(smemc);
    const uint32_t oA = 0, oAl = 32768, oVH = 65536, oVL = 81920;  // 96K

    const int tid = threadIdx.x;
    const int wid = tid >> 5, lane = tid & 31;
    const int ch = blockIdx.x >> 2, vsl = blockIdx.x & 3;
    const int h = blockIdx.y, bb = blockIdx.z;
    const int m0 = bb * TT + ch * CHUNK;
    const int colQ = h * 128;
    const int colV = h * 256 + vsl * 64;
    const size_t chA = (size_t)((bb * NCH + ch) * HH + h) * 16384;
    const size_t ublob = (size_t)(((bb * HH + h) * 4 + vsl) * NCH + ch) * 8192;
    const int mw = (wid & 3) * 32, nw = (wid >> 2) * 32;

#pragma unroll
    for (int l = 0; l < 8; l++) {
        int idx = tid + (l << 8);
        int row = idx >> 4, u = idx & 15;
        int kb = u >> 3, sub = u & 7;
        uint32_t dst = (uint32_t)kb * 16384u + sw128((uint32_t)(row << 7) + (sub << 4));
        size_t sa = chA + (size_t)row * 128 + kb * 64 + sub * 8;
        cpasync16(sb + oA  + dst, AH + sa);
        cpasync16(sb + oAl + dst, AL + sa);
    }
    asm volatile("cp.async.commit_group;" ::: "memory");

#pragma unroll
    for (int l = 0; l < 16; l++) {
        int idx = tid + (l << 8);
        int j = idx >> 5, n = (idx & 31) << 1;
        uint32_t wv = *(const uint32_t*)(VH + (size_t)(m0 + j) * DD + colV + n);
        uint32_t wl = *(const uint32_t*)(VL + (size_t)(m0 + j) * DD + colV + n);
        uint32_t kbo = (uint32_t)(j >> 6) * 8192u;
        uint32_t off0 = kbo + sw128((uint32_t)(n << 7) + ((j & 63) << 1));
        uint32_t off1 = kbo + sw128((uint32_t)((n + 1) << 7) + ((j & 63) << 1));
        *(unsigned short*)(smemc + oVH + off0) = (unsigned short)(wv & 0xffff);
        *(unsigned short*)(smemc + oVH + off1) = (unsigned short)(wv >> 16);
        *(unsigned short*)(smemc + oVL + off0) = (unsigned short)(wl & 0xffff);
        *(unsigned short*)(smemc + oVL + off1) = (unsigned short)(wl >> 16);
    }
    asm volatile("cp.async.wait_group 0;" ::: "memory");
    __syncthreads();

    float acc[2][4][4];
#pragma unroll
    for (int i = 0; i < 2; i++)
#pragma unroll
        for (int j = 0; j < 4; j++)
#pragma unroll
            for (int l = 0; l < 4; l++) acc[i][j][l] = 0.f;
    mma_combo<2>(acc, sb + oA,  16384, sb + oVH, 8192, mw, nw, lane);
    mma_combo<2>(acc, sb + oA,  16384, sb + oVL, 8192, mw, nw, lane);
    mma_combo<2>(acc, sb + oAl, 16384, sb + oVH, 8192, mw, nw, lane);
#pragma unroll
    for (int mf = 0; mf < 2; mf++) {
#pragma unroll
        for (int half = 0; half < 2; half++) {
            int row = m0 + mw + mf * 16 + half * 8 + (lane >> 2);
#pragma unroll
            for (int nf = 0; nf < 4; nf++) {
                int col = colV + nw + nf * 8 + ((lane & 3) << 1);
                float2 v;
                v.x = acc[mf][nf][half * 2 + 0];
                v.y = acc[mf][nf][half * 2 + 1];
                *(float2*)&O[(size_t)row * DD + col] = v;
            }
        }
    }
    __syncthreads();

#pragma unroll
    for (int l = 0; l < 32; l++) {
        int idx = tid + (l << 8);
        int j = idx >> 6, d = (idx & 63) << 1;
        uint32_t wv = *(const uint32_t*)(KDH + (size_t)(m0 + j) * DHALF + colQ + d);
        uint32_t wl = *(const uint32_t*)(KDL + (size_t)(m0 + j) * DHALF + colQ + d);
        uint32_t kbo = (uint32_t)(j >> 6) * 16384u;
        uint32_t off0 = kbo + sw128((uint32_t)(d << 7) + ((j & 63) << 1));
        uint32_t off1 = kbo + sw128((uint32_t)((d + 1) << 7) + ((j & 63) << 1));
        *(unsigned short*)(smemc + oA  + off0) = (unsigned short)(wv & 0xffff);
        *(unsigned short*)(smemc + oA  + off1) = (unsigned short)(wv >> 16);
        *(unsigned short*)(smemc + oAl + off0) = (unsigned short)(wl & 0xffff);
        *(unsigned short*)(smemc + oAl + off1) = (unsigned short)(wl >> 16);
    }
    __syncthreads();

    float uacc[2][4][4];
#pragma unroll
    for (int i = 0; i < 2; i++)
#pragma unroll
        for (int j = 0; j < 4; j++)
#pragma unroll
            for (int l = 0; l < 4; l++) uacc[i][j][l] = 0.f;
    mma_combo<2>(uacc, sb + oA,  16384, sb + oVH, 8192, mw, nw, lane);
    mma_combo<2>(uacc, sb + oA,  16384, sb + oVL, 8192, mw, nw, lane);
    mma_combo<2>(uacc, sb + oAl, 16384, sb + oVH, 8192, mw, nw, lane);
#pragma unroll
    for (int mf = 0; mf < 2; mf++) {
#pragma unroll
        for (int half = 0; half < 2; half++) {
            int d = mw + mf * 16 + half * 8 + (lane >> 2);
            uint32_t kb = (uint32_t)(d >> 6) * 4096u;
            uint32_t d2b = (uint32_t)((d & 63) << 1);
#pragma unroll
            for (int nf = 0; nf < 4; nf++) {
                int n = nw + nf * 8 + ((lane & 3) << 1);
                uint32_t i0 = kb + (sw128(((uint32_t)n << 7) + d2b) >> 1);
                uint32_t i1 = kb + (sw128(((uint32_t)(n + 1) << 7) + d2b) >> 1);
                U[ublob + i0] = uacc[mf][nf][half * 2 + 0];
                U[ublob + i1] = uacc[mf][nf][half * 2 + 1];
            }
        }
    }
}

// ======================================================================
// scan (verified R11)
// ======================================================================
__global__ __launch_bounds__(256, 1)
void scan_kernel(const float* __restrict__ U, const float* __restrict__ DEC,
                 __nv_bfloat16* __restrict__ SBH, __nv_bfloat16* __restrict__ SBL)
{
    __shared__ float sdec[128];
    const int t = threadIdx.x;
    const int vsl = blockIdx.x, h = blockIdx.y, bb = blockIdx.z;
    const int blobbase = ((bb * HH + h) * 4 + vsl) * NCH;
    const int colQ = h * 128;

    int dbase[8];
#pragma unroll
    for (int g = 0; g < 8; g++) {
        uint32_t ibase = (uint32_t)(t + g * 256) * 4;
        uint32_t braw = sw128((ibase & 4095) * 2);
        dbase[g] = (int)(ibase >> 12) * 64 + (int)((braw & 127) >> 1);
    }

    float S[32];
#pragma unroll
    for (int i = 0; i < 32; i++) S[i] = 0.f;

    for (int ch = 0; ch < NCH; ch++) {
        if (t < 128) sdec[t] = DEC[(size_t)(bb * NCH + ch) * DHALF + colQ + t];
        const size_t blob = (size_t)(blobbase + ch) * 8192;
#pragma unroll
        for (int g = 0; g < 8; g++) {
            uint32_t ibase = (uint32_t)(t + g * 256) * 4;
            float v0 = S[g * 4 + 0], v1 = S[g * 4 + 1], v2 = S[g * 4 + 2], v3 = S[g * 4 + 3];
            __nv_bfloat16 h0 = __float2bfloat16(v0), h1 = __float2bfloat16(v1);
            __nv_bfloat16 h2 = __float2bfloat16(v2), h3 = __float2bfloat16(v3);
            *(__nv_bfloat162*)(SBH + blob + ibase)     = __nv_bfloat162(h0, h1);
            *(__nv_bfloat162*)(SBH + blob + ibase + 2) = __nv_bfloat162(h2, h3);
            __nv_bfloat16 l0 = __float2bfloat16(v0 - __bfloat162float(h0));
            __nv_bfloat16 l1 = __float2bfloat16(v1 - __bfloat162float(h1));
            __nv_bfloat16 l2 = __float2bfloat16(v2 - __bfloat162float(h2));
            __nv_bfloat16 l3 = __float2bfloat16(v3 - __bfloat162float(h3));
            *(__nv_bfloat162*)(SBL + blob + ibase)     = __nv_bfloat162(l0, l1);
            *(__nv_bfloat162*)(SBL + blob + ibase + 2) = __nv_bfloat162(l2, l3);
        }
        __syncthreads();
#pragma unroll
        for (int g = 0; g < 8; g++) {
            uint32_t ibase = (uint32_t)(t + g * 256) * 4;
            float4 u = *(const float4*)(U + blob + ibase);
            int d0 = dbase[g];
            S[g * 4 + 0] = sdec[d0 + 0] * S[g * 4 + 0] + u.x;
            S[g * 4 + 1] = sdec[d0 + 1] * S[g * 4 + 1] + u.y;
            S[g * 4 + 2] = sdec[d0 + 2] * S[g * 4 + 2] + u.z;
            S[g * 4 + 3] = sdec[d0 + 3] * S[g * 4 + 3] + u.w;
        }
        __syncthreads();
    }
}

// ======================================================================
// o2 (verified R11): O += qd @ S_ch
// ======================================================================
__global__ __launch_bounds__(256, 1)
void o2_kernel(const __nv_bfloat16* __restrict__ QH, const __nv_bfloat16* __restrict__ QL,
               const __nv_bfloat16* __restrict__ SBH, const __nv_bfloat16* __restrict__ SBL,
               float* __restrict__ O)
{
    extern __shared__ char smemc[];
    const uint32_t sb = smem_u32(smemc);
    const uint32_t oQH = 0, oQL = 32768, oSH = 65536, oSL = 81920;

    const int tid = threadIdx.x;
    const int wid = tid >> 5, lane = tid & 31;
    const int ch = blockIdx.x >> 2, vsl = blockIdx.x & 3;
    const int h = blockIdx.y, bb = blockIdx.z;
    const int m0 = bb * TT + ch * CHUNK;
    const int colQ = h * 128;
    const int colV = h * 256 + vsl * 64;
    const size_t blob = (size_t)(((bb * HH + h) * 4 + vsl) * NCH + ch) * 8192;
    const int mw = (wid & 3) * 32, nw = (wid >> 2) * 32;

#pragma unroll
    for (int l = 0; l < 8; l++) {
        int idx = tid + (l << 8);
        int row = idx >> 4, u = idx & 15;
        int kb = u >> 3, sub = u & 7;
        uint32_t dst = (uint32_t)kb * 16384u + sw128((uint32_t)(row << 7) + (sub << 4));
        size_t so = (size_t)(m0 + row) * DHALF + colQ + kb * 64 + sub * 8;
        cpasync16(sb + oQH + dst, QH + so);
        cpasync16(sb + oQL + dst, QL + so);
    }
#pragma unroll
    for (int l = 0; l < 4; l++) {
        int i = tid + (l << 8);
        cpasync16(sb + oSH + (i << 4), SBH + blob + (size_t)i * 8);
        cpasync16(sb + oSL + (i << 4), SBL + blob + (size_t)i * 8);
    }
    asm volatile("cp.async.commit_group;" ::: "memory");
    asm volatile("cp.async.wait_group 0;" ::: "memory");
    __syncthreads();

    float acc[2][4][4];
#pragma unroll
    for (int i = 0; i < 2; i++)
#pragma unroll
        for (int j = 0; j < 4; j++)
#pragma unroll
            for (int l = 0; l < 4; l++) acc[i][j][l] = 0.f;

    mma_combo<2>(acc, sb + oQH, 16384, sb + oSH, 8192, mw, nw, lane);
    mma_combo<2>(acc, sb + oQH, 16384, sb + oSL, 8192, mw, nw, lane);
    mma_combo<2>(acc, sb + oQL, 16384, sb + oSH, 8192, mw, nw, lane);

#pragma unroll
    for (int mf = 0; mf < 2; mf++) {
#pragma unroll
        for (int half = 0; half < 2; half++) {
            int row = m0 + mw + mf * 16 + half * 8 + (lane >> 2);
#pragma unroll
            for (int nf = 0; nf < 4; nf++) {
                int col = colV + nw + nf * 8 + ((lane & 3) << 1);
                float2 v = *(float2*)&O[(size_t)row * DD + col];
                v.x += acc[mf][nf][half * 2 + 0];
                v.y += acc[mf][nf][half * 2 + 1];
                *(float2*)&O[(size_t)row * DD + col] = v;
            }
        }
    }
}

// ======================================================================
// x -> fp16
// ======================================================================
__global__ void xhalf(const float4* __restrict__ X, __half* __restrict__ H, int n4)
{
    int i = blockIdx.x * blockDim.x + threadIdx.x;
    if (i >= n4) return;
    float4 v = X[i];
    __half2* Hp = (__half2*)H;
    Hp[i * 2]     = __floats2half2_rn(v.x, v.y);
    Hp[i * 2 + 1] = __floats2half2_rn(v.z, v.w);
}

// ======================================================================
// transpose W -> combined WT fp16 (single precision level)
// ======================================================================
__global__ void wsplit_t(const float* __restrict__ W, __half* __restrict__ Th,
                         int K, int N, int rowoff, float alpha)
{
    __shared__ float t[32][33];
    const int n0 = blockIdx.x * 32, k0 = blockIdx.y * 32;
    const int tx = threadIdx.x, ty = threadIdx.y;
#pragma unroll
    for (int i = 0; i < 4; i++) {
        int k = ty + i * 8;
        t[k][tx] = W[(size_t)(k0 + k) * N + n0 + tx];
    }
    __syncthreads();
#pragma unroll
    for (int i = 0; i < 4; i++) {
        int n = ty + i * 8;
        float v = t[tx][n] * alpha;
        Th[(size_t)(rowoff + n0 + n) * K + k0 + tx] = __float2half(v);
    }
}

// ======================================================================
// kg1
// ======================================================================
__global__ void kg1_kernel(const float* __restrict__ x, const float* __restrict__ W1,
                           float* __restrict__ out)
{
    const int wid = threadIdx.x >> 5, lane = threadIdx.x & 31;
    const int row = blockIdx.x * 8 + wid;
    const float* xp = x + (size_t)row * DD;
    float acc[16];
#pragma unroll
    for (int c = 0; c < 16; c++) acc[c] = 0.f;
    for (int k = lane; k < DD; k += 32) {
        float xv = xp[k];
        const float4* wp = (const float4*)(W1 + (size_t)k * 16);
        float4 w0 = wp[0], w1 = wp[1], w2 = wp[2], w3 = wp[3];
        acc[0]  += xv * w0.x; acc[1]  += xv * w0.y; acc[2]  += xv * w0.z; acc[3]  += xv * w0.w;
        acc[4]  += xv * w1.x; acc[5]  += xv * w1.y; acc[6]  += xv * w1.z; acc[7]  += xv * w1.w;
        acc[8]  += xv * w2.x; acc[9]  += xv * w2.y; acc[10] += xv * w2.z; acc[11] += xv * w2.w;
        acc[12] += xv * w3.x; acc[13] += xv * w3.y; acc[14] += xv * w3.z; acc[15] += xv * w3.w;
    }
#pragma unroll
    for (int c = 0; c < 16; c++) {
        float v = acc[c];
#pragma unroll
        for (int off = 16; off; off >>= 1) v += __shfl_xor_sync(0xFFFFFFFFu, v, off);
        if (lane == 0) out[(size_t)row * 16 + c] = v;
    }
}

// ======================================================================
// gk
// ======================================================================
__global__ void gk_kernel(const float* __restrict__ KG1,
                          const float* __restrict__ W2,
                          const float* __restrict__ b2,
                          float* __restrict__ GK)
{
    __shared__ float a[16];
    int m = blockIdx.x;
    if (threadIdx.x < 16) a[threadIdx.x] = KG1[(size_t)m * 16 + threadIdx.x];
    __syncthreads();
    for (int c = threadIdx.x; c < DHALF; c += 128) {
        float z = b2[c];
#pragma unroll
        for (int r = 0; r < 16; r++) z = fmaf(a[r], W2[(size_t)r * DHALF + c], z);
        float e = __expf(-fabsf(z));
        float l = __logf(1.f + e);
        float ls = (z >= 0.f) ? -l : (z - l);
        GK[(size_t)m * DHALF + c] = ls * INV_NORM_GK;
    }
}

// ======================================================================
// prep
// ======================================================================
__global__ void prep_kernel(const float* __restrict__ QK,
                            const float* __restrict__ GK,
                            __nv_bfloat16* __restrict__ QHo, __nv_bfloat16* __restrict__ QLo,
                            __nv_bfloat16* __restrict__ KHo, __nv_bfloat16* __restrict__ KLo,
                            __nv_bfloat16* __restrict__ KDHo, __nv_bfloat16* __restrict__ KDLo,
                            float* __restrict__ DEC)
{
    int g = blockIdx.x * blockDim.x + threadIdx.x;
    int col = g & (DHALF - 1);
    int bc  = g >> 10;
    int row0 = ((bc >> 4) * TT) + ((bc & 15) * CHUNK);
    size_t baseg = (size_t)row0 * DHALF + col;
    size_t baseq = (size_t)row0 * 2048 + col;

    float gs = 0.f;
#pragma unroll 4
    for (int i = 0; i < CHUNK; i++) gs += GK[baseg + (size_t)i * DHALF];
    float egs = __expf(gs);

    float gc = 0.f;
    for (int i = 0; i < CHUNK; i++) {
        size_t idx = baseg + (size_t)i * DHALF;
        size_t qdx = baseq + (size_t)i * 2048;
        gc += GK[idx];
        float eg = __expf(gc);
        float qd = QK[qdx] * eg;
        float kv = QK[qdx + 1024];
        float ke = __fdividef(kv, eg);
        float kd = ke * egs;
        __nv_bfloat16 qh = __float2bfloat16(qd);
        __nv_bfloat16 kh = __float2bfloat16(ke);
        __nv_bfloat16 dh = __float2bfloat16(kd);
        QHo[idx]  = qh; QLo[idx]  = __float2bfloat16(qd - __bfloat162float(qh));
        KHo[idx]  = kh; KLo[idx]  = __float2bfloat16(ke - __bfloat162float(kh));
        KDHo[idx] = dh; KDLo[idx] = __float2bfloat16(kd - __bfloat162float(dh));
    }
    DEC[(size_t)bc * DHALF + col] = egs;
}

// ======================================================================
// norm * silu -> fp16
// ======================================================================
__global__ void norm_gate_kernel(const float* __restrict__ O,
                                 const float* __restrict__ G,
                                 __half* __restrict__ PH)
{
    int m = blockIdx.x, h = blockIdx.y;
    int tid = threadIdx.x;
    size_t idx = (size_t)m * DD + h * DV + tid;
    float v = O[idx];
    float s = v, s2 = v * v;
#pragma unroll
    for (int off = 16; off; off >>= 1) {
        s  += __shfl_xor_sync(0xFFFFFFFFu, s,  off);
        s2 += __shfl_xor_sync(0xFFFFFFFFu, s2, off);
    }
    __shared__ float ws[8], ws2[8];
    int w = tid >> 5, l = tid & 31;
    if (l == 0) { ws[w] = s; ws2[w] = s2; }
    __syncthreads();
    float ts = 0.f, ts2 = 0.f;
#pragma unroll
    for (int i = 0; i < 8; i++) { ts += ws[i]; ts2 += ws2[i]; }
    float mu = ts * (1.f / 256.f);
    float var = ts2 * (1.f / 256.f) - mu * mu;
    float nv = (v - mu) * rsqrtf(var + 1e-5f);
    float gt = G[idx];
    float sg = gt / (1.f + __expf(-gt));
    PH[idx] = __float2half(sg * nv);
}

// ======================================================================
extern "C" void kernel_launch(void* const* d_in, const int* in_sizes, int n_in,
                              void* d_out, int out_size)
{
    const float* x    = (const float*)d_in[0];
    const float* Wq   = (const float*)d_in[1];
    const float* Wk   = (const float*)d_in[2];
    const float* Wkg1 = (const float*)d_in[3];
    const float* Wkg2 = (const float*)d_in[4];
    const float* bkg2 = (const float*)d_in[5];
    const float* Wv   = (const float*)d_in[6];
    const float* Wg   = (const float*)d_in[7];
    const float* bg   = (const float*)d_in[8];
    const float* Wo   = (const float*)d_in[9];
    float* out = (float*)d_out;

    float *pQK, *pGK, *pKG1, *pDEC, *pG, *pO, *pU;
    __half *pXH, *pWTH, *pPH;
    __nv_bfloat16 *pQH, *pQL, *pKH, *pKL, *pKDH, *pKDL, *pVH, *pVL, *pAH, *pAL, *pSBH, *pSBL;
    cudaGetSymbolAddress((void**)&pQK,  g_QK);
    cudaGetSymbolAddress((void**)&pGK,  g_GK);
    cudaGetSymbolAddress((void**)&pKG1, g_KG1);
    cudaGetSymbolAddress((void**)&pDEC, g_DEC);
    cudaGetSymbolAddress((void**)&pG,   g_G);
    cudaGetSymbolAddress((void**)&pO,   g_O);
    cudaGetSymbolAddress((void**)&pU,   g_U);
    cudaGetSymbolAddress((void**)&pXH,  g_XH);
    cudaGetSymbolAddress((void**)&pWTH, g_WTH);
    cudaGetSymbolAddress((void**)&pPH,  g_PH);
    cudaGetSymbolAddress((void**)&pQH,  g_QH);
    cudaGetSymbolAddress((void**)&pQL,  g_QL);
    cudaGetSymbolAddress((void**)&pKH,  g_KH);
    cudaGetSymbolAddress((void**)&pKL,  g_KL);
    cudaGetSymbolAddress((void**)&pKDH, g_KDH);
    cudaGetSymbolAddress((void**)&pKDL, g_KDL);
    cudaGetSymbolAddress((void**)&pVH,  g_VH);
    cudaGetSymbolAddress((void**)&pVL,  g_VL);
    cudaGetSymbolAddress((void**)&pAH,  g_AH);
    cudaGetSymbolAddress((void**)&pAL,  g_AL);
    cudaGetSymbolAddress((void**)&pSBH, g_SBH);
    cudaGetSymbolAddress((void**)&pSBL, g_SBL);

    cudaFuncSetAttribute(gemm1h,        cudaFuncAttributeMaxDynamicSharedMemorySize, 98304);
    cudaFuncSetAttribute(akernel,       cudaFuncAttributeMaxDynamicSharedMemorySize, 131072);
    cudaFuncSetAttribute(phase1_kernel, cudaFuncAttributeMaxDynamicSharedMemorySize, 98304);
    cudaFuncSetAttribute(o2_kernel,     cudaFuncAttributeMaxDynamicSharedMemorySize, 98304);

    dim3 tb(32, 8);
    int n4 = MROWS * DD / 4;

    // x -> fp16 ; weights -> combined WT fp16 (Q|K*scale|V|G|O)
    xhalf<<<(n4 + 255) / 256, 256>>>((const float4*)x, pXH, n4);
    kg1_kernel<<<MROWS / 8, 256>>>(x, Wkg1, pKG1);
    wsplit_t<<<dim3(DHALF / 32, DD / 32), tb>>>(Wq, pWTH, DD, DHALF, 0, 1.0f);
    wsplit_t<<<dim3(DHALF / 32, DD / 32), tb>>>(Wk, pWTH, DD, DHALF, 1024, SCALING);
    wsplit_t<<<dim3(DD / 32, DD / 32), tb>>>(Wv, pWTH, DD, DD, 2048, 1.0f);
    wsplit_t<<<dim3(DD / 32, DD / 32), tb>>>(Wg, pWTH, DD, DD, 4096, 1.0f);
    wsplit_t<<<dim3(DD / 32, DD / 32), tb>>>(Wo, pWTH, DD, DD, 6144, 1.0f);

    // fused Q+K+V+G projection (N=6144, single-pass): QK fp32 | V bf16-split | G fp32+bias
    gemm1h<<<dim3(6144 / 128, MROWS / 128), 256, 98304>>>(pXH, pWTH,
        pQK, pVH, pVL, pG, bg, MROWS, 6144, DD, 2048, 4096);

    // gk + decay precompute
    gk_kernel<<<MROWS, 128>>>(pKG1, Wkg2, bkg2, pGK);
    prep_kernel<<<256, 256>>>(pQK, pGK, pQH, pQL, pKH, pKL, pKDH, pKDL, pDEC);

    // A chunks
    akernel<<<dim3(HH, NCH, BB), 256, 131072>>>(pQH, pQL, pKH, pKL, pAH, pAL);

    // parallel: O_intra + U chunks
    phase1_kernel<<<dim3(NCH * 4, HH, BB), 256, 98304>>>(pAH, pAL, pKDH, pKDL,
                                                         pVH, pVL, pO, pU);
    // fast elementwise scan -> S blobs
    scan_kernel<<<dim3(4, HH, BB), 256>>>(pU, pDEC, pSBH, pSBL);
    // parallel: O += qd @ S
    o2_kernel<<<dim3(NCH * 4, HH, BB), 256, 98304>>>(pQH, pQL, pSBH, pSBL, pO);

    // groupnorm + silu gate -> fp16
    norm_gate_kernel<<<dim3(MROWS, HH), 256>>>(pO, pG, pPH);

    // output projection (single-pass, fp32 out)
    gemm1h<<<dim3(2048 / 128, MROWS / 128), 256, 98304>>>(pPH,
        pWTH + (size_t)6144 * DD,
        out, nullptr, nullptr, nullptr, nullptr, MROWS, 2048, DD, 2048, 2048);
}